// round 5
// baseline (speedup 1.0000x reference)
#include <cuda_runtime.h>
#include <cstdint>

// Problem dims
#define Tn  4096          // tokens (B*S)
#define Hd  2048          // hidden
#define En  8             // experts
#define Id  1024          // expert intermediate
#define ISd 4096          // shared intermediate

// GEMM tile config
#define BM 128
#define BN 64
#define BK 16
#define TPB 256

typedef unsigned long long ull;

// ---------------- scratch (device globals; no runtime allocation) ----------
__device__ int   g_cnt[En];
__device__ int   g_list[En * Tn];                    // pair ids per expert
__device__ float g_scores[Tn * 2];                   // sigmoid gate per pair
__device__ float g_Hm[(size_t)Tn * 2 * Id];          // silu(g)*u per pair
__device__ float g_Y[(size_t)Tn * 2 * Hd];           // routed partial per pair
__device__ float g_Smid[(size_t)Tn * ISd];           // shared-expert mid

// ---------------- helpers --------------------------------------------------
__device__ __forceinline__ void fma2(ull &d, ull a, ull b) {
    asm("fma.rn.f32x2 %0, %1, %2, %0;" : "+l"(d) : "l"(a), "l"(b));
}
__device__ __forceinline__ float f2lo(ull v) { return __uint_as_float((unsigned)v); }
__device__ __forceinline__ float f2hi(ull v) { return __uint_as_float((unsigned)(v >> 32)); }
__device__ __forceinline__ ull fdup(float x) {
    unsigned u = __float_as_uint(x);
    return ((ull)u << 32) | (ull)u;
}
__device__ __forceinline__ float siluf(float x) { return x / (1.f + expf(-x)); }

// ---------------- kernel: zero counters ------------------------------------
__global__ void k_zero() {
    if (threadIdx.x < En) g_cnt[threadIdx.x] = 0;
}

// ---------------- kernel: router + top2 + list build -----------------------
// one block per token, 8 warps = 8 experts
__global__ void k_router(const float* __restrict__ x,
                         const float* __restrict__ rw,
                         float* __restrict__ logits) {
    int t = blockIdx.x;
    int w = threadIdx.x >> 5, lane = threadIdx.x & 31;
    const float* xt = x + (size_t)t * Hd;
    const float* we = rw + (size_t)w * Hd;
    float s = 0.f;
    for (int i = lane * 4; i < Hd; i += 128) {
        float4 xv = *(const float4*)(xt + i);
        float4 wv = *(const float4*)(we + i);
        s += xv.x * wv.x + xv.y * wv.y + xv.z * wv.z + xv.w * wv.w;
    }
    #pragma unroll
    for (int o = 16; o; o >>= 1) s += __shfl_xor_sync(0xffffffffu, s, o);
    __shared__ float lg[En];
    if (!lane) lg[w] = s;
    __syncthreads();
    if (threadIdx.x == 0) {
        #pragma unroll
        for (int e = 0; e < En; e++) logits[(size_t)t * En + e] = lg[e];
        int i0 = 0; float v0 = lg[0];
        #pragma unroll
        for (int e = 1; e < En; e++) if (lg[e] > v0) { v0 = lg[e]; i0 = e; }
        int i1 = -1; float v1 = -3.4e38f;
        #pragma unroll
        for (int e = 0; e < En; e++) if (e != i0 && lg[e] > v1) { v1 = lg[e]; i1 = e; }
        float s0 = 1.f / (1.f + expf(-v0));
        float s1 = 1.f / (1.f + expf(-v1));
        int p0 = t * 2, p1 = t * 2 + 1;
        g_scores[p0] = s0; g_scores[p1] = s1;
        int pos0 = atomicAdd(&g_cnt[i0], 1); g_list[i0 * Tn + pos0] = p0;
        int pos1 = atomicAdd(&g_cnt[i1], 1); g_list[i1 * Tn + pos1] = p1;
    }
}

// ---------------- kernel: per-expert gate/up fused GEMM ---------------------
// C tile: [BM rows of expert token list] x [BN cols of I]; K over Hd
__global__ __launch_bounds__(TPB) void k_expert_gateup(
    const float* __restrict__ x,
    const float* __restrict__ gate_w,
    const float* __restrict__ up_w) {
    const int e = blockIdx.z;
    const int cnt = g_cnt[e];
    const int m0 = blockIdx.x * BM;
    if (m0 >= cnt) return;
    const int n0 = blockIdx.y * BN;
    const int* list = g_list + e * Tn;
    const float* Bg = gate_w + (size_t)e * Id * Hd;
    const float* Bu = up_w   + (size_t)e * Id * Hd;

    __shared__ __align__(16) float As[BK][BM];
    __shared__ __align__(16) float Bgs[BK][2 * BN];
    __shared__ __align__(16) float Bus[BK][2 * BN];

    const int tid = threadIdx.x;
    const int a_r = tid >> 1, a_k = (tid & 1) * 8;
    const int b_n = tid >> 2, b_k = (tid & 3) * 4;
    const int tr = tid & 15, tc = tid >> 4;
    const int r0 = tr * 8, c0 = tc * 4;

    const int arow = m0 + a_r;
    const float* aptr = nullptr;
    if (arow < cnt) aptr = x + (size_t)(list[arow] >> 1) * Hd;
    const float* bgp = Bg + (size_t)(n0 + b_n) * Hd + b_k;
    const float* bup = Bu + (size_t)(n0 + b_n) * Hd + b_k;

    ull accG[4][4], accU[4][4];
    #pragma unroll
    for (int q = 0; q < 4; q++)
        #pragma unroll
        for (int j = 0; j < 4; j++) { accG[q][j] = 0ull; accU[q][j] = 0ull; }

    for (int k0 = 0; k0 < Hd; k0 += BK) {
        float4 av0, av1;
        if (aptr) {
            av0 = *(const float4*)(aptr + k0 + a_k);
            av1 = *(const float4*)(aptr + k0 + a_k + 4);
        } else {
            av0 = make_float4(0.f, 0.f, 0.f, 0.f); av1 = av0;
        }
        float4 bgv = *(const float4*)(bgp + k0);
        float4 buv = *(const float4*)(bup + k0);
        __syncthreads();
        As[a_k + 0][a_r] = av0.x; As[a_k + 1][a_r] = av0.y;
        As[a_k + 2][a_r] = av0.z; As[a_k + 3][a_r] = av0.w;
        As[a_k + 4][a_r] = av1.x; As[a_k + 5][a_r] = av1.y;
        As[a_k + 6][a_r] = av1.z; As[a_k + 7][a_r] = av1.w;
        ((ull*)Bgs[b_k + 0])[b_n] = fdup(bgv.x);
        ((ull*)Bgs[b_k + 1])[b_n] = fdup(bgv.y);
        ((ull*)Bgs[b_k + 2])[b_n] = fdup(bgv.z);
        ((ull*)Bgs[b_k + 3])[b_n] = fdup(bgv.w);
        ((ull*)Bus[b_k + 0])[b_n] = fdup(buv.x);
        ((ull*)Bus[b_k + 1])[b_n] = fdup(buv.y);
        ((ull*)Bus[b_k + 2])[b_n] = fdup(buv.z);
        ((ull*)Bus[b_k + 3])[b_n] = fdup(buv.w);
        __syncthreads();
        #pragma unroll
        for (int k = 0; k < BK; k++) {
            ulonglong2 a01 = *(const ulonglong2*)&As[k][r0];
            ulonglong2 a23 = *(const ulonglong2*)&As[k][r0 + 4];
            ull ap[4] = {a01.x, a01.y, a23.x, a23.y};
            ulonglong2 bg01 = *(const ulonglong2*)&Bgs[k][2 * c0];
            ulonglong2 bg23 = *(const ulonglong2*)&Bgs[k][2 * c0 + 4];
            ull bg4[4] = {bg01.x, bg01.y, bg23.x, bg23.y};
            ulonglong2 bu01 = *(const ulonglong2*)&Bus[k][2 * c0];
            ulonglong2 bu23 = *(const ulonglong2*)&Bus[k][2 * c0 + 4];
            ull bu4[4] = {bu01.x, bu01.y, bu23.x, bu23.y};
            #pragma unroll
            for (int q = 0; q < 4; q++)
                #pragma unroll
                for (int j = 0; j < 4; j++) {
                    fma2(accG[q][j], ap[q], bg4[j]);
                    fma2(accU[q][j], ap[q], bu4[j]);
                }
        }
    }
    // epilogue: h = silu(s*g) * (s*u) -> g_Hm[pair][col]
    #pragma unroll
    for (int q = 0; q < 4; q++) {
        int rbase = m0 + r0 + 2 * q;
        #pragma unroll
        for (int hh = 0; hh < 2; hh++) {
            int row = rbase + hh;
            if (row < cnt) {
                int p = list[row];
                float s = g_scores[p];
                float gv[4], uv[4];
                #pragma unroll
                for (int j = 0; j < 4; j++) {
                    gv[j] = hh ? f2hi(accG[q][j]) : f2lo(accG[q][j]);
                    uv[j] = hh ? f2hi(accU[q][j]) : f2lo(accU[q][j]);
                }
                float4 o;
                o.x = siluf(s * gv[0]) * (s * uv[0]);
                o.y = siluf(s * gv[1]) * (s * uv[1]);
                o.z = siluf(s * gv[2]) * (s * uv[2]);
                o.w = siluf(s * gv[3]) * (s * uv[3]);
                *(float4*)(&g_Hm[(size_t)p * Id + n0 + c0]) = o;
            }
        }
    }
}

// ---------------- kernel: per-expert down GEMM ------------------------------
// Y[pair, h] = Hm[pair, :] . down_e[h, :], K over Id
__global__ __launch_bounds__(TPB) void k_expert_down(
    const float* __restrict__ down_w) {
    const int e = blockIdx.z;
    const int cnt = g_cnt[e];
    const int m0 = blockIdx.x * BM;
    if (m0 >= cnt) return;
    const int n0 = blockIdx.y * BN;
    const int* list = g_list + e * Tn;
    const float* Bd = down_w + (size_t)e * Hd * Id;

    __shared__ __align__(16) float As[BK][BM];
    __shared__ __align__(16) float Bs[BK][2 * BN];

    const int tid = threadIdx.x;
    const int a_r = tid >> 1, a_k = (tid & 1) * 8;
    const int b_n = tid >> 2, b_k = (tid & 3) * 4;
    const int tr = tid & 15, tc = tid >> 4;
    const int r0 = tr * 8, c0 = tc * 4;

    const int arow = m0 + a_r;
    const float* aptr = nullptr;
    int ap_p = 0;
    if (arow < cnt) { ap_p = list[arow]; aptr = g_Hm + (size_t)ap_p * Id; }
    const float* bp = Bd + (size_t)(n0 + b_n) * Id + b_k;

    ull acc[4][4];
    #pragma unroll
    for (int q = 0; q < 4; q++)
        #pragma unroll
        for (int j = 0; j < 4; j++) acc[q][j] = 0ull;

    for (int k0 = 0; k0 < Id; k0 += BK) {
        float4 av0, av1;
        if (aptr) {
            av0 = *(const float4*)(aptr + k0 + a_k);
            av1 = *(const float4*)(aptr + k0 + a_k + 4);
        } else {
            av0 = make_float4(0.f, 0.f, 0.f, 0.f); av1 = av0;
        }
        float4 bv = *(const float4*)(bp + k0);
        __syncthreads();
        As[a_k + 0][a_r] = av0.x; As[a_k + 1][a_r] = av0.y;
        As[a_k + 2][a_r] = av0.z; As[a_k + 3][a_r] = av0.w;
        As[a_k + 4][a_r] = av1.x; As[a_k + 5][a_r] = av1.y;
        As[a_k + 6][a_r] = av1.z; As[a_k + 7][a_r] = av1.w;
        ((ull*)Bs[b_k + 0])[b_n] = fdup(bv.x);
        ((ull*)Bs[b_k + 1])[b_n] = fdup(bv.y);
        ((ull*)Bs[b_k + 2])[b_n] = fdup(bv.z);
        ((ull*)Bs[b_k + 3])[b_n] = fdup(bv.w);
        __syncthreads();
        #pragma unroll
        for (int k = 0; k < BK; k++) {
            ulonglong2 a01 = *(const ulonglong2*)&As[k][r0];
            ulonglong2 a23 = *(const ulonglong2*)&As[k][r0 + 4];
            ull ap[4] = {a01.x, a01.y, a23.x, a23.y};
            ulonglong2 b01 = *(const ulonglong2*)&Bs[k][2 * c0];
            ulonglong2 b23 = *(const ulonglong2*)&Bs[k][2 * c0 + 4];
            ull b4[4] = {b01.x, b01.y, b23.x, b23.y};
            #pragma unroll
            for (int q = 0; q < 4; q++)
                #pragma unroll
                for (int j = 0; j < 4; j++) fma2(acc[q][j], ap[q], b4[j]);
        }
    }
    #pragma unroll
    for (int q = 0; q < 4; q++) {
        int rbase = m0 + r0 + 2 * q;
        #pragma unroll
        for (int hh = 0; hh < 2; hh++) {
            int row = rbase + hh;
            if (row < cnt) {
                int p = list[row];
                float4 o;
                o.x = hh ? f2hi(acc[q][0]) : f2lo(acc[q][0]);
                o.y = hh ? f2hi(acc[q][1]) : f2lo(acc[q][1]);
                o.z = hh ? f2hi(acc[q][2]) : f2lo(acc[q][2]);
                o.w = hh ? f2hi(acc[q][3]) : f2lo(acc[q][3]);
                *(float4*)(&g_Y[(size_t)p * Hd + n0 + c0]) = o;
            }
        }
    }
}

// ---------------- kernel: shared-expert gate/up fused GEMM ------------------
__global__ __launch_bounds__(TPB) void k_shared_gateup(
    const float* __restrict__ x,
    const float* __restrict__ sgw,
    const float* __restrict__ suw) {
    const int m0 = blockIdx.x * BM;
    const int n0 = blockIdx.y * BN;

    __shared__ __align__(16) float As[BK][BM];
    __shared__ __align__(16) float Bgs[BK][2 * BN];
    __shared__ __align__(16) float Bus[BK][2 * BN];

    const int tid = threadIdx.x;
    const int a_r = tid >> 1, a_k = (tid & 1) * 8;
    const int b_n = tid >> 2, b_k = (tid & 3) * 4;
    const int tr = tid & 15, tc = tid >> 4;
    const int r0 = tr * 8, c0 = tc * 4;

    const float* aptr = x + (size_t)(m0 + a_r) * Hd;
    const float* bgp = sgw + (size_t)(n0 + b_n) * Hd + b_k;
    const float* bup = suw + (size_t)(n0 + b_n) * Hd + b_k;

    ull accG[4][4], accU[4][4];
    #pragma unroll
    for (int q = 0; q < 4; q++)
        #pragma unroll
        for (int j = 0; j < 4; j++) { accG[q][j] = 0ull; accU[q][j] = 0ull; }

    for (int k0 = 0; k0 < Hd; k0 += BK) {
        float4 av0 = *(const float4*)(aptr + k0 + a_k);
        float4 av1 = *(const float4*)(aptr + k0 + a_k + 4);
        float4 bgv = *(const float4*)(bgp + k0);
        float4 buv = *(const float4*)(bup + k0);
        __syncthreads();
        As[a_k + 0][a_r] = av0.x; As[a_k + 1][a_r] = av0.y;
        As[a_k + 2][a_r] = av0.z; As[a_k + 3][a_r] = av0.w;
        As[a_k + 4][a_r] = av1.x; As[a_k + 5][a_r] = av1.y;
        As[a_k + 6][a_r] = av1.z; As[a_k + 7][a_r] = av1.w;
        ((ull*)Bgs[b_k + 0])[b_n] = fdup(bgv.x);
        ((ull*)Bgs[b_k + 1])[b_n] = fdup(bgv.y);
        ((ull*)Bgs[b_k + 2])[b_n] = fdup(bgv.z);
        ((ull*)Bgs[b_k + 3])[b_n] = fdup(bgv.w);
        ((ull*)Bus[b_k + 0])[b_n] = fdup(buv.x);
        ((ull*)Bus[b_k + 1])[b_n] = fdup(buv.y);
        ((ull*)Bus[b_k + 2])[b_n] = fdup(buv.z);
        ((ull*)Bus[b_k + 3])[b_n] = fdup(buv.w);
        __syncthreads();
        #pragma unroll
        for (int k = 0; k < BK; k++) {
            ulonglong2 a01 = *(const ulonglong2*)&As[k][r0];
            ulonglong2 a23 = *(const ulonglong2*)&As[k][r0 + 4];
            ull ap[4] = {a01.x, a01.y, a23.x, a23.y};
            ulonglong2 bg01 = *(const ulonglong2*)&Bgs[k][2 * c0];
            ulonglong2 bg23 = *(const ulonglong2*)&Bgs[k][2 * c0 + 4];
            ull bg4[4] = {bg01.x, bg01.y, bg23.x, bg23.y};
            ulonglong2 bu01 = *(const ulonglong2*)&Bus[k][2 * c0];
            ulonglong2 bu23 = *(const ulonglong2*)&Bus[k][2 * c0 + 4];
            ull bu4[4] = {bu01.x, bu01.y, bu23.x, bu23.y};
            #pragma unroll
            for (int q = 0; q < 4; q++)
                #pragma unroll
                for (int j = 0; j < 4; j++) {
                    fma2(accG[q][j], ap[q], bg4[j]);
                    fma2(accU[q][j], ap[q], bu4[j]);
                }
        }
    }
    #pragma unroll
    for (int q = 0; q < 4; q++) {
        int rbase = m0 + r0 + 2 * q;
        #pragma unroll
        for (int hh = 0; hh < 2; hh++) {
            int t = rbase + hh;
            float gv[4], uv[4];
            #pragma unroll
            for (int j = 0; j < 4; j++) {
                gv[j] = hh ? f2hi(accG[q][j]) : f2lo(accG[q][j]);
                uv[j] = hh ? f2hi(accU[q][j]) : f2lo(accU[q][j]);
            }
            float4 o;
            o.x = siluf(gv[0]) * uv[0];
            o.y = siluf(gv[1]) * uv[1];
            o.z = siluf(gv[2]) * uv[2];
            o.w = siluf(gv[3]) * uv[3];
            *(float4*)(&g_Smid[(size_t)t * ISd + n0 + c0]) = o;
        }
    }
}

// ---------------- kernel: shared-expert down GEMM + final combine -----------
__global__ __launch_bounds__(TPB) void k_shared_down(
    const float* __restrict__ sdw,
    float* __restrict__ out) {
    const int m0 = blockIdx.x * BM;
    const int n0 = blockIdx.y * BN;

    __shared__ __align__(16) float As[BK][BM];
    __shared__ __align__(16) float Bs[BK][2 * BN];

    const int tid = threadIdx.x;
    const int a_r = tid >> 1, a_k = (tid & 1) * 8;
    const int b_n = tid >> 2, b_k = (tid & 3) * 4;
    const int tr = tid & 15, tc = tid >> 4;
    const int r0 = tr * 8, c0 = tc * 4;

    const float* aptr = g_Smid + (size_t)(m0 + a_r) * ISd;
    const float* bp = sdw + (size_t)(n0 + b_n) * ISd + b_k;

    ull acc[4][4];
    #pragma unroll
    for (int q = 0; q < 4; q++)
        #pragma unroll
        for (int j = 0; j < 4; j++) acc[q][j] = 0ull;

    for (int k0 = 0; k0 < ISd; k0 += BK) {
        float4 av0 = *(const float4*)(aptr + k0 + a_k);
        float4 av1 = *(const float4*)(aptr + k0 + a_k + 4);
        float4 bv = *(const float4*)(bp + k0);
        __syncthreads();
        As[a_k + 0][a_r] = av0.x; As[a_k + 1][a_r] = av0.y;
        As[a_k + 2][a_r] = av0.z; As[a_k + 3][a_r] = av0.w;
        As[a_k + 4][a_r] = av1.x; As[a_k + 5][a_r] = av1.y;
        As[a_k + 6][a_r] = av1.z; As[a_k + 7][a_r] = av1.w;
        ((ull*)Bs[b_k + 0])[b_n] = fdup(bv.x);
        ((ull*)Bs[b_k + 1])[b_n] = fdup(bv.y);
        ((ull*)Bs[b_k + 2])[b_n] = fdup(bv.z);
        ((ull*)Bs[b_k + 3])[b_n] = fdup(bv.w);
        __syncthreads();
        #pragma unroll
        for (int k = 0; k < BK; k++) {
            ulonglong2 a01 = *(const ulonglong2*)&As[k][r0];
            ulonglong2 a23 = *(const ulonglong2*)&As[k][r0 + 4];
            ull ap[4] = {a01.x, a01.y, a23.x, a23.y};
            ulonglong2 b01 = *(const ulonglong2*)&Bs[k][2 * c0];
            ulonglong2 b23 = *(const ulonglong2*)&Bs[k][2 * c0 + 4];
            ull b4[4] = {b01.x, b01.y, b23.x, b23.y};
            #pragma unroll
            for (int q = 0; q < 4; q++)
                #pragma unroll
                for (int j = 0; j < 4; j++) fma2(acc[q][j], ap[q], b4[j]);
        }
    }
    #pragma unroll
    for (int q = 0; q < 4; q++) {
        int rbase = m0 + r0 + 2 * q;
        #pragma unroll
        for (int hh = 0; hh < 2; hh++) {
            int t = rbase + hh;
            const float* y0p = &g_Y[(size_t)(2 * t) * Hd + n0 + c0];
            const float* y1p = &g_Y[(size_t)(2 * t + 1) * Hd + n0 + c0];
            float4 y0 = *(const float4*)y0p;
            float4 y1 = *(const float4*)y1p;
            float4 o;
            o.x = (hh ? f2hi(acc[q][0]) : f2lo(acc[q][0])) + y0.x + y1.x;
            o.y = (hh ? f2hi(acc[q][1]) : f2lo(acc[q][1])) + y0.y + y1.y;
            o.z = (hh ? f2hi(acc[q][2]) : f2lo(acc[q][2])) + y0.z + y1.z;
            o.w = (hh ? f2hi(acc[q][3]) : f2lo(acc[q][3])) + y0.w + y1.w;
            *(float4*)(&out[(size_t)t * Hd + n0 + c0]) = o;
        }
    }
}

// ---------------- launch ----------------------------------------------------
extern "C" void kernel_launch(void* const* d_in, const int* in_sizes, int n_in,
                              void* d_out, int out_size) {
    const float* x   = (const float*)d_in[0];
    const float* rw  = (const float*)d_in[1];
    const float* gw  = (const float*)d_in[2];
    const float* uw  = (const float*)d_in[3];
    const float* dw  = (const float*)d_in[4];
    const float* sgw = (const float*)d_in[5];
    const float* suw = (const float*)d_in[6];
    const float* sdw = (const float*)d_in[7];
    float* out = (float*)d_out;
    float* logits = out + (size_t)Tn * Hd;

    k_zero<<<1, 32>>>();
    k_router<<<Tn, 256>>>(x, rw, logits);
    k_expert_gateup<<<dim3(Tn / BM, Id / BN, En), TPB>>>(x, gw, uw);
    k_expert_down<<<dim3(Tn / BM, Hd / BN, En), TPB>>>(dw);
    k_shared_gateup<<<dim3(Tn / BM, ISd / BN), TPB>>>(x, sgw, suw);
    k_shared_down<<<dim3(Tn / BM, Hd / BN), TPB>>>(sdw, out);
}

// round 9
// speedup vs baseline: 2.9676x; 2.9676x over previous
#include <cuda_runtime.h>
#include <cuda_bf16.h>
#include <cstdint>

#define Tn  4096
#define Hd  2048
#define En  8
#define Id  1024
#define ISd 4096

#define BM 128
#define BN 128
#define BKC 32            // bf16 k per chunk
#define NTH 256

// smem: stage st at st*32768: A tile 16KB (128 rows x [32 hi | 32 lo] bf16 = 128B rows),
//       B tile 16KB at +16384. list at 65536.
#define SM_STAGE 32768
#define SM_BOFF  16384
#define SM_LIST  65536
#define SMEM_BYTES 66048

typedef unsigned uns;

// ---------------- device scratch -------------------------------------------
__device__ int   g_cnt[En];
__device__ int   g_list[En * Tn];
__device__ float g_scores[Tn * 2];
__device__ float g_G[(size_t)Tn * ISd];               // gate scratch (reused)
__device__ __nv_bfloat16 g_HmH[(size_t)Tn * 2 * Id];
__device__ __nv_bfloat16 g_HmL[(size_t)Tn * 2 * Id];
__device__ __nv_bfloat16 g_SmH[(size_t)Tn * ISd];
__device__ __nv_bfloat16 g_SmL[(size_t)Tn * ISd];
__device__ float g_Y[(size_t)Tn * 2 * Hd];

// ---------------- helpers --------------------------------------------------
__device__ __forceinline__ uint32_t smem_u32(const void* p) {
    uint32_t a;
    asm("{ .reg .u64 t; cvta.to.shared.u64 t, %1; cvt.u32.u64 %0, t; }" : "=r"(a) : "l"(p));
    return a;
}
__device__ __forceinline__ void ldsm4(uns r[4], uint32_t a) {
    asm volatile("ldmatrix.sync.aligned.m8n8.x4.shared.b16 {%0,%1,%2,%3}, [%4];"
        : "=r"(r[0]), "=r"(r[1]), "=r"(r[2]), "=r"(r[3]) : "r"(a));
}
__device__ __forceinline__ void ldsm2(uns r[2], uint32_t a) {
    asm volatile("ldmatrix.sync.aligned.m8n8.x2.shared.b16 {%0,%1}, [%2];"
        : "=r"(r[0]), "=r"(r[1]) : "r"(a));
}
__device__ __forceinline__ void mma16816(float c[4], const uns a[4], const uns b[2]) {
    asm volatile("mma.sync.aligned.m16n8k16.row.col.f32.bf16.bf16.f32 "
        "{%0,%1,%2,%3}, {%4,%5,%6,%7}, {%8,%9}, {%0,%1,%2,%3};"
        : "+f"(c[0]), "+f"(c[1]), "+f"(c[2]), "+f"(c[3])
        : "r"(a[0]), "r"(a[1]), "r"(a[2]), "r"(a[3]), "r"(b[0]), "r"(b[1]));
}
__device__ __forceinline__ void split2(float a, float b, uns &hi, uns &lo) {
    __nv_bfloat162 h = __floats2bfloat162_rn(a, b);
    float2 hf = __bfloat1622float2(h);
    __nv_bfloat162 l = __floats2bfloat162_rn(a - hf.x, b - hf.y);
    hi = *reinterpret_cast<uns*>(&h);
    lo = *reinterpret_cast<uns*>(&l);
}
__device__ __forceinline__ float siluf(float x) { return x / (1.f + expf(-x)); }

// ---------------- router -----------------------------------------------------
__global__ void k_zero() {
    if (threadIdx.x < En) g_cnt[threadIdx.x] = 0;
}

__global__ void k_router(const float* __restrict__ x,
                         const float* __restrict__ rw,
                         float* __restrict__ logits) {
    int t = blockIdx.x;
    int w = threadIdx.x >> 5, lane = threadIdx.x & 31;
    const float* xt = x + (size_t)t * Hd;
    const float* we = rw + (size_t)w * Hd;
    float s = 0.f;
    for (int i = lane * 4; i < Hd; i += 128) {
        float4 xv = *(const float4*)(xt + i);
        float4 wv = *(const float4*)(we + i);
        s += xv.x * wv.x + xv.y * wv.y + xv.z * wv.z + xv.w * wv.w;
    }
    #pragma unroll
    for (int o = 16; o; o >>= 1) s += __shfl_xor_sync(0xffffffffu, s, o);
    __shared__ float lg[En];
    if (!lane) lg[w] = s;
    __syncthreads();
    if (threadIdx.x == 0) {
        #pragma unroll
        for (int e = 0; e < En; e++) logits[(size_t)t * En + e] = lg[e];
        int i0 = 0; float v0 = lg[0];
        #pragma unroll
        for (int e = 1; e < En; e++) if (lg[e] > v0) { v0 = lg[e]; i0 = e; }
        int i1 = -1; float v1 = -3.4e38f;
        #pragma unroll
        for (int e = 0; e < En; e++) if (e != i0 && lg[e] > v1) { v1 = lg[e]; i1 = e; }
        int p0 = t * 2, p1 = t * 2 + 1;
        g_scores[p0] = 1.f / (1.f + expf(-v0));
        g_scores[p1] = 1.f / (1.f + expf(-v1));
        int pos0 = atomicAdd(&g_cnt[i0], 1); g_list[i0 * Tn + pos0] = p0;
        int pos1 = atomicAdd(&g_cnt[i1], 1); g_list[i1 * Tn + pos1] = p1;
    }
}

// ---------------- unified mma.sync GEMM --------------------------------------
// MODE 0: expert gate  A=x(gather)       B=gate_w[e]  K=2048 -> g_G (pair-major)
// MODE 1: expert up    A=x(gather)       B=up_w[e]    K=2048 -> HmH/L (silu w/ g_G)
// MODE 2: shared gate  A=x               B=sgw        K=2048 -> g_G (token-major)
// MODE 3: shared up    A=x               B=suw        K=2048 -> SmH/L (silu w/ g_G)
// MODE 4: expert down  A=Hm (pre-split)  B=down_w[e]  K=1024 -> g_Y
// MODE 5: shared down  A=Sm (pre-split)  B=sdw        K=4096 -> out (+Y combine)
template<int MODE>
__global__ __launch_bounds__(NTH, 1) void k_gemm(
    const float* __restrict__ x,
    const float* __restrict__ w,
    float* __restrict__ out) {
    extern __shared__ __align__(1024) char smem[];
    const uint32_t sb = smem_u32(smem);
    const int tid = threadIdx.x, wid = tid >> 5, lane = tid & 31;

    constexpr bool EXP  = (MODE == 0 || MODE == 1 || MODE == 4);
    constexpr bool F32A = (MODE <= 3);           // A source fp32 (needs split)
    constexpr int  KT   = (MODE == 4) ? 1024 : (MODE == 5 ? 4096 : 2048);
    constexpr int  NKC  = KT / BKC;

    const int e   = EXP ? blockIdx.z : 0;
    const int cnt = EXP ? g_cnt[e] : Tn;
    const int m0  = blockIdx.x * BM;
    if (EXP && m0 >= cnt) return;
    const int n0  = blockIdx.y * BN;

    int* sl = (int*)(smem + SM_LIST);
    if (EXP) {
        if (tid < 128) sl[tid] = (m0 + tid < cnt) ? g_list[e * Tn + m0 + tid] : -1;
        __syncthreads();
    }

    // ---- per-thread gmem source setup (row = tid>>1, sub = tid&1) ----
    const int arow = tid >> 1, asub = tid & 1;
    bool aval = true;
    const float* aF = nullptr;
    const __nv_bfloat16* aB = nullptr;
    if (MODE == 0 || MODE == 1) {
        int p = sl[arow]; aval = (p >= 0);
        aF = x + (size_t)(aval ? (p >> 1) : 0) * Hd + asub * 16;
    } else if (MODE == 2 || MODE == 3) {
        aF = x + (size_t)(m0 + arow) * Hd + asub * 16;
    } else if (MODE == 4) {
        int p = sl[arow]; aval = (p >= 0);
        aB = (asub ? g_HmL : g_HmH) + (size_t)(aval ? p : 0) * Id;
    } else {
        aB = (asub ? g_SmL : g_SmH) + (size_t)(m0 + arow) * ISd;
    }
    const float* bF;
    if (MODE == 0 || MODE == 1)      bF = w + ((size_t)e * Id + n0 + arow) * Hd + asub * 16;
    else if (MODE == 2 || MODE == 3) bF = w + (size_t)(n0 + arow) * Hd + asub * 16;
    else if (MODE == 4)              bF = w + ((size_t)e * Hd + n0 + arow) * Id + asub * 16;
    else                             bF = w + (size_t)(n0 + arow) * ISd + asub * 16;

    // ---- smem store bases (generic pointers!) ----
    const uint32_t vst = (uint32_t)(arow & 7) << 4;
    char* aRowP = smem + arow * 128;
    char* bRowP = smem + SM_BOFF + arow * 128;

    // ---- mma-side ldmatrix bases (.shared addresses) ----
    const int wm = wid & 3, wn = wid >> 2;
    const uint32_t vA   = (uint32_t)(lane & 7) << 4;
    const uint32_t aLmB = (wm * 32 + (lane & 15)) * 128;
    const uint32_t aLmK = (lane >> 4) * 16;
    const uint32_t bLmB = SM_BOFF + (wn * 64 + (lane & 7)) * 128;
    const uint32_t bLmK = ((lane >> 3) & 1) * 16;

    float acc[2][8][4];
    #pragma unroll
    for (int mt = 0; mt < 2; mt++)
        #pragma unroll
        for (int nt = 0; nt < 8; nt++)
            #pragma unroll
            for (int j = 0; j < 4; j++) acc[mt][nt][j] = 0.f;

    float4 ar[4], br[4];
    uint4  aq[4];

    // ---- load chunk into regs ----
    auto LD = [&](int kc) {
        if (F32A) {
            #pragma unroll
            for (int i = 0; i < 4; i++)
                ar[i] = aval ? *(const float4*)(aF + kc * 32 + i * 4)
                             : make_float4(0.f, 0.f, 0.f, 0.f);
        } else {
            #pragma unroll
            for (int i = 0; i < 4; i++)
                aq[i] = aval ? *(const uint4*)((const char*)aB + kc * 64 + i * 16)
                             : make_uint4(0u, 0u, 0u, 0u);
        }
        #pragma unroll
        for (int i = 0; i < 4; i++)
            br[i] = *(const float4*)(bF + kc * 32 + i * 4);
    };
    // ---- split + store regs into smem stage (16B stores, generic ptrs) ----
    auto ST = [&](int st) {
        char* aS = aRowP + st * SM_STAGE;
        char* bS = bRowP + st * SM_STAGE;
        if (F32A) {
            #pragma unroll
            for (int ii = 0; ii < 2; ii++) {
                uns h0, l0, h1, l1, h2, l2, h3, l3;
                split2(ar[2 * ii].x,     ar[2 * ii].y,     h0, l0);
                split2(ar[2 * ii].z,     ar[2 * ii].w,     h1, l1);
                split2(ar[2 * ii + 1].x, ar[2 * ii + 1].y, h2, l2);
                split2(ar[2 * ii + 1].z, ar[2 * ii + 1].w, h3, l3);
                uint32_t gh = (uint32_t)(asub * 32 + ii * 16) ^ vst;
                uint32_t gl = (uint32_t)(64 + asub * 32 + ii * 16) ^ vst;
                *(uint4*)(aS + gh) = make_uint4(h0, h1, h2, h3);
                *(uint4*)(aS + gl) = make_uint4(l0, l1, l2, l3);
            }
        } else {
            #pragma unroll
            for (int i = 0; i < 4; i++)
                *(uint4*)(aS + ((uint32_t)(asub * 64 + i * 16) ^ vst)) = aq[i];
        }
        #pragma unroll
        for (int ii = 0; ii < 2; ii++) {
            uns h0, l0, h1, l1, h2, l2, h3, l3;
            split2(br[2 * ii].x,     br[2 * ii].y,     h0, l0);
            split2(br[2 * ii].z,     br[2 * ii].w,     h1, l1);
            split2(br[2 * ii + 1].x, br[2 * ii + 1].y, h2, l2);
            split2(br[2 * ii + 1].z, br[2 * ii + 1].w, h3, l3);
            uint32_t gh = (uint32_t)(asub * 32 + ii * 16) ^ vst;
            uint32_t gl = (uint32_t)(64 + asub * 32 + ii * 16) ^ vst;
            *(uint4*)(bS + gh) = make_uint4(h0, h1, h2, h3);
            *(uint4*)(bS + gl) = make_uint4(l0, l1, l2, l3);
        }
    };
    // ---- mma on stage ----
    auto MMA = [&](int st) {
        const uint32_t aS = sb + st * SM_STAGE;
        #pragma unroll
        for (int h = 0; h < 2; h++) {
            uns Ah[2][4], Al[2][4];
            #pragma unroll
            for (int mt = 0; mt < 2; mt++) {
                ldsm4(Ah[mt], aS + aLmB + mt * 2048 + ((h * 32 + aLmK) ^ vA));
                ldsm4(Al[mt], aS + aLmB + mt * 2048 + ((64 + h * 32 + aLmK) ^ vA));
            }
            #pragma unroll
            for (int nt = 0; nt < 8; nt++) {
                uns Bh[2], Bl[2];
                ldsm2(Bh, aS + bLmB + nt * 1024 + ((h * 32 + bLmK) ^ vA));
                ldsm2(Bl, aS + bLmB + nt * 1024 + ((64 + h * 32 + bLmK) ^ vA));
                #pragma unroll
                for (int mt = 0; mt < 2; mt++) {
                    mma16816(acc[mt][nt], Ah[mt], Bh);
                    mma16816(acc[mt][nt], Ah[mt], Bl);
                    mma16816(acc[mt][nt], Al[mt], Bh);
                }
            }
        }
    };

    LD(0); ST(0); __syncthreads();
    for (int kc = 0; kc < NKC; kc++) {
        const int st = kc & 1;
        if (kc + 1 < NKC) LD(kc + 1);
        MMA(st);
        if (kc + 1 < NKC) { ST(st ^ 1); __syncthreads(); }
    }

    // ---- epilogue ----
    const int rb = wm * 32 + (lane >> 2);
    const int cb = wn * 64 + (lane & 3) * 2;
    #pragma unroll
    for (int mt = 0; mt < 2; mt++) {
        #pragma unroll
        for (int rr = 0; rr < 2; rr++) {
            const int row = rb + mt * 16 + rr * 8;     // local 0..127
            if (MODE == 0 || MODE == 1 || MODE == 4) {
                int p = sl[row];
                if (p < 0) continue;
                if (MODE == 0) {
                    float* dst = g_G + (size_t)p * Id + n0 + cb;
                    #pragma unroll
                    for (int nt = 0; nt < 8; nt++)
                        *(float2*)(dst + nt * 8) =
                            make_float2(acc[mt][nt][rr * 2], acc[mt][nt][rr * 2 + 1]);
                } else if (MODE == 1) {
                    float s = g_scores[p];
                    size_t base = (size_t)p * Id + n0 + cb;
                    #pragma unroll
                    for (int nt = 0; nt < 8; nt++) {
                        float2 g2 = *(const float2*)(g_G + base + nt * 8);
                        float u0 = acc[mt][nt][rr * 2], u1 = acc[mt][nt][rr * 2 + 1];
                        float h0 = siluf(s * g2.x) * (s * u0);
                        float h1 = siluf(s * g2.y) * (s * u1);
                        uns phi, plo; split2(h0, h1, phi, plo);
                        *(uns*)(g_HmH + base + nt * 8) = phi;
                        *(uns*)(g_HmL + base + nt * 8) = plo;
                    }
                } else {  // MODE 4
                    float* dst = g_Y + (size_t)p * Hd + n0 + cb;
                    #pragma unroll
                    for (int nt = 0; nt < 8; nt++)
                        *(float2*)(dst + nt * 8) =
                            make_float2(acc[mt][nt][rr * 2], acc[mt][nt][rr * 2 + 1]);
                }
            } else {
                const int t = m0 + row;
                if (MODE == 2) {
                    float* dst = g_G + (size_t)t * ISd + n0 + cb;
                    #pragma unroll
                    for (int nt = 0; nt < 8; nt++)
                        *(float2*)(dst + nt * 8) =
                            make_float2(acc[mt][nt][rr * 2], acc[mt][nt][rr * 2 + 1]);
                } else if (MODE == 3) {
                    size_t base = (size_t)t * ISd + n0 + cb;
                    #pragma unroll
                    for (int nt = 0; nt < 8; nt++) {
                        float2 g2 = *(const float2*)(g_G + base + nt * 8);
                        float u0 = acc[mt][nt][rr * 2], u1 = acc[mt][nt][rr * 2 + 1];
                        float h0 = siluf(g2.x) * u0;
                        float h1 = siluf(g2.y) * u1;
                        uns phi, plo; split2(h0, h1, phi, plo);
                        *(uns*)(g_SmH + base + nt * 8) = phi;
                        *(uns*)(g_SmL + base + nt * 8) = plo;
                    }
                } else {  // MODE 5
                    size_t col = n0 + cb;
                    const float* y0 = g_Y + (size_t)(2 * t) * Hd + col;
                    const float* y1 = g_Y + (size_t)(2 * t + 1) * Hd + col;
                    float* dst = out + (size_t)t * Hd + col;
                    #pragma unroll
                    for (int nt = 0; nt < 8; nt++) {
                        float2 a = make_float2(acc[mt][nt][rr * 2], acc[mt][nt][rr * 2 + 1]);
                        float2 p0 = *(const float2*)(y0 + nt * 8);
                        float2 p1 = *(const float2*)(y1 + nt * 8);
                        a.x += p0.x + p1.x; a.y += p0.y + p1.y;
                        *(float2*)(dst + nt * 8) = a;
                    }
                }
            }
        }
    }
}

// ---------------- launch ----------------------------------------------------
extern "C" void kernel_launch(void* const* d_in, const int* in_sizes, int n_in,
                              void* d_out, int out_size) {
    const float* x   = (const float*)d_in[0];
    const float* rw  = (const float*)d_in[1];
    const float* gw  = (const float*)d_in[2];
    const float* uw  = (const float*)d_in[3];
    const float* dw  = (const float*)d_in[4];
    const float* sgw = (const float*)d_in[5];
    const float* suw = (const float*)d_in[6];
    const float* sdw = (const float*)d_in[7];
    float* out = (float*)d_out;
    float* logits = out + (size_t)Tn * Hd;

    cudaFuncSetAttribute(k_gemm<0>, cudaFuncAttributeMaxDynamicSharedMemorySize, SMEM_BYTES);
    cudaFuncSetAttribute(k_gemm<1>, cudaFuncAttributeMaxDynamicSharedMemorySize, SMEM_BYTES);
    cudaFuncSetAttribute(k_gemm<2>, cudaFuncAttributeMaxDynamicSharedMemorySize, SMEM_BYTES);
    cudaFuncSetAttribute(k_gemm<3>, cudaFuncAttributeMaxDynamicSharedMemorySize, SMEM_BYTES);
    cudaFuncSetAttribute(k_gemm<4>, cudaFuncAttributeMaxDynamicSharedMemorySize, SMEM_BYTES);
    cudaFuncSetAttribute(k_gemm<5>, cudaFuncAttributeMaxDynamicSharedMemorySize, SMEM_BYTES);

    k_zero<<<1, 32>>>();
    k_router<<<Tn, 256>>>(x, rw, logits);

    k_gemm<0><<<dim3(Tn / BM, Id / BN, En),  NTH, SMEM_BYTES>>>(x, gw, nullptr);
    k_gemm<1><<<dim3(Tn / BM, Id / BN, En),  NTH, SMEM_BYTES>>>(x, uw, nullptr);
    k_gemm<4><<<dim3(Tn / BM, Hd / BN, En),  NTH, SMEM_BYTES>>>(nullptr, dw, nullptr);
    k_gemm<2><<<dim3(Tn / BM, ISd / BN, 1),  NTH, SMEM_BYTES>>>(x, sgw, nullptr);
    k_gemm<3><<<dim3(Tn / BM, ISd / BN, 1),  NTH, SMEM_BYTES>>>(x, suw, nullptr);
    k_gemm<5><<<dim3(Tn / BM, Hd / BN, 1),   NTH, SMEM_BYTES>>>(nullptr, sdw, out);
}

// round 10
// speedup vs baseline: 3.5200x; 1.1862x over previous
#include <cuda_runtime.h>
#include <cuda_bf16.h>
#include <cstdint>

#define Tn  4096
#define Hd  2048
#define En  8
#define Id  1024
#define ISd 4096

#define BM 128
#define BN 128
#define NTH 256

// smem: stage st at st*32768: A tile 16KB (128 rows x [32 hi | 32 lo] bf16 = 128B rows),
//       B tile 16KB at +16384. list at 65536.
#define SM_STAGE 32768
#define SM_BOFF  16384
#define SM_LIST  65536
#define SMEM_BYTES 66048

typedef unsigned uns;

// ---------------- device scratch -------------------------------------------
__device__ int   g_cnt[En];
__device__ int   g_list[En * Tn];
__device__ float g_scores[Tn * 2];
__device__ float g_G[(size_t)Tn * ISd];
__device__ __nv_bfloat16 g_HmH[(size_t)Tn * 2 * Id];
__device__ __nv_bfloat16 g_HmL[(size_t)Tn * 2 * Id];
__device__ __nv_bfloat16 g_SmH[(size_t)Tn * ISd];
__device__ __nv_bfloat16 g_SmL[(size_t)Tn * ISd];
__device__ float g_Y[(size_t)Tn * 2 * Hd];
// pre-split bf16 operands
__device__ __nv_bfloat16 g_xH[(size_t)Tn * Hd],        g_xL[(size_t)Tn * Hd];
__device__ __nv_bfloat16 g_gwH[(size_t)En * Id * Hd],  g_gwL[(size_t)En * Id * Hd];
__device__ __nv_bfloat16 g_uwH[(size_t)En * Id * Hd],  g_uwL[(size_t)En * Id * Hd];
__device__ __nv_bfloat16 g_dwH[(size_t)En * Hd * Id],  g_dwL[(size_t)En * Hd * Id];
__device__ __nv_bfloat16 g_sgwH[(size_t)ISd * Hd],     g_sgwL[(size_t)ISd * Hd];
__device__ __nv_bfloat16 g_suwH[(size_t)ISd * Hd],     g_suwL[(size_t)ISd * Hd];
__device__ __nv_bfloat16 g_sdwH[(size_t)Hd * ISd],     g_sdwL[(size_t)Hd * ISd];

// ---------------- helpers --------------------------------------------------
__device__ __forceinline__ uint32_t smem_u32(const void* p) {
    uint32_t a;
    asm("{ .reg .u64 t; cvta.to.shared.u64 t, %1; cvt.u32.u64 %0, t; }" : "=r"(a) : "l"(p));
    return a;
}
__device__ __forceinline__ void ldsm4(uns r[4], uint32_t a) {
    asm volatile("ldmatrix.sync.aligned.m8n8.x4.shared.b16 {%0,%1,%2,%3}, [%4];"
        : "=r"(r[0]), "=r"(r[1]), "=r"(r[2]), "=r"(r[3]) : "r"(a));
}
__device__ __forceinline__ void mma16816(float c[4], const uns a[4], const uns b[2]) {
    asm volatile("mma.sync.aligned.m16n8k16.row.col.f32.bf16.bf16.f32 "
        "{%0,%1,%2,%3}, {%4,%5,%6,%7}, {%8,%9}, {%0,%1,%2,%3};"
        : "+f"(c[0]), "+f"(c[1]), "+f"(c[2]), "+f"(c[3])
        : "r"(a[0]), "r"(a[1]), "r"(a[2]), "r"(a[3]), "r"(b[0]), "r"(b[1]));
}
__device__ __forceinline__ void cpa16(uint32_t d, const void* s, uint32_t bytes) {
    asm volatile("cp.async.ca.shared.global [%0], [%1], 16, %2;"
        :: "r"(d), "l"(s), "r"(bytes) : "memory");
}
__device__ __forceinline__ void cpcommit() {
    asm volatile("cp.async.commit_group;" ::: "memory");
}
template<int N> __device__ __forceinline__ void cpwait() {
    asm volatile("cp.async.wait_group %0;" :: "n"(N) : "memory");
}
__device__ __forceinline__ void split2(float a, float b, uns &hi, uns &lo) {
    __nv_bfloat162 h = __floats2bfloat162_rn(a, b);
    float2 hf = __bfloat1622float2(h);
    __nv_bfloat162 l = __floats2bfloat162_rn(a - hf.x, b - hf.y);
    hi = *reinterpret_cast<uns*>(&h);
    lo = *reinterpret_cast<uns*>(&l);
}
__device__ __forceinline__ float siluf(float x) { return x / (1.f + expf(-x)); }

// ---------------- pre-split fp32 -> bf16 hi/lo ------------------------------
__global__ void k_split(const float4* __restrict__ in,
                        uint2* __restrict__ oh, uint2* __restrict__ ol, int n4) {
    int i = blockIdx.x * blockDim.x + threadIdx.x;
    if (i < n4) {
        float4 v = in[i];
        uns h0, l0, h1, l1;
        split2(v.x, v.y, h0, l0);
        split2(v.z, v.w, h1, l1);
        oh[i] = make_uint2(h0, h1);
        ol[i] = make_uint2(l0, l1);
    }
}

// ---------------- router -----------------------------------------------------
__global__ void k_zero() {
    if (threadIdx.x < En) g_cnt[threadIdx.x] = 0;
}

__global__ void k_router(const float* __restrict__ x,
                         const float* __restrict__ rw,
                         float* __restrict__ logits) {
    int t = blockIdx.x;
    int w = threadIdx.x >> 5, lane = threadIdx.x & 31;
    const float* xt = x + (size_t)t * Hd;
    const float* we = rw + (size_t)w * Hd;
    float s = 0.f;
    for (int i = lane * 4; i < Hd; i += 128) {
        float4 xv = *(const float4*)(xt + i);
        float4 wv = *(const float4*)(we + i);
        s += xv.x * wv.x + xv.y * wv.y + xv.z * wv.z + xv.w * wv.w;
    }
    #pragma unroll
    for (int o = 16; o; o >>= 1) s += __shfl_xor_sync(0xffffffffu, s, o);
    __shared__ float lg[En];
    if (!lane) lg[w] = s;
    __syncthreads();
    if (threadIdx.x == 0) {
        #pragma unroll
        for (int e = 0; e < En; e++) logits[(size_t)t * En + e] = lg[e];
        int i0 = 0; float v0 = lg[0];
        #pragma unroll
        for (int e = 1; e < En; e++) if (lg[e] > v0) { v0 = lg[e]; i0 = e; }
        int i1 = -1; float v1 = -3.4e38f;
        #pragma unroll
        for (int e = 0; e < En; e++) if (e != i0 && lg[e] > v1) { v1 = lg[e]; i1 = e; }
        int p0 = t * 2, p1 = t * 2 + 1;
        g_scores[p0] = 1.f / (1.f + expf(-v0));
        g_scores[p1] = 1.f / (1.f + expf(-v1));
        int pos0 = atomicAdd(&g_cnt[i0], 1); g_list[i0 * Tn + pos0] = p0;
        int pos1 = atomicAdd(&g_cnt[i1], 1); g_list[i1 * Tn + pos1] = p1;
    }
}

// ---------------- unified mma.sync GEMM (all bf16 pre-split, cp.async) -------
// MODE 0: expert gate  A=x(gather)  B=gate_w[e]  K=2048 -> g_G
// MODE 1: expert up    A=x(gather)  B=up_w[e]    K=2048 -> HmH/L (silu w/ g_G)
// MODE 2: shared gate  A=x          B=sgw        K=2048 -> g_G
// MODE 3: shared up    A=x          B=suw        K=2048 -> SmH/L (silu w/ g_G)
// MODE 4: expert down  A=Hm         B=down_w[e]  K=1024 -> g_Y
// MODE 5: shared down  A=Sm         B=sdw        K=4096 -> out (+Y combine)
template<int MODE>
__global__ __launch_bounds__(NTH, 2) void k_gemm(float* __restrict__ out) {
    extern __shared__ __align__(1024) char smem[];
    const uint32_t sb = smem_u32(smem);
    const int tid = threadIdx.x, wid = tid >> 5, lane = tid & 31;

    constexpr bool EXP = (MODE == 0 || MODE == 1 || MODE == 4);
    constexpr int  KT  = (MODE == 4) ? 1024 : (MODE == 5 ? 4096 : 2048);
    constexpr int  NKC = KT / 32;

    const int e   = EXP ? blockIdx.z : 0;
    const int cnt = EXP ? g_cnt[e] : Tn;
    const int m0  = blockIdx.x * BM;
    if (EXP && m0 >= cnt) return;
    const int n0  = blockIdx.y * BN;

    int* sl = (int*)(smem + SM_LIST);
    if (EXP) {
        if (tid < 128) sl[tid] = (m0 + tid < cnt) ? g_list[e * Tn + m0 + tid] : -1;
        __syncthreads();
    }

    // ---- per-thread cp.async source rows (row = tid>>1, sub = tid&1) ----
    const int arow = tid >> 1, sub = tid & 1;
    bool aval = true;
    const __nv_bfloat16 *aH, *aL, *bH, *bL;
    if (MODE == 0 || MODE == 1) {
        int p = sl[arow]; aval = (p >= 0);
        size_t r = (size_t)(aval ? (p >> 1) : 0) * Hd;
        aH = g_xH + r; aL = g_xL + r;
    } else if (MODE == 2 || MODE == 3) {
        size_t r = (size_t)(m0 + arow) * Hd;
        aH = g_xH + r; aL = g_xL + r;
    } else if (MODE == 4) {
        int p = sl[arow]; aval = (p >= 0);
        size_t r = (size_t)(aval ? p : 0) * Id;
        aH = g_HmH + r; aL = g_HmL + r;
    } else {
        size_t r = (size_t)(m0 + arow) * ISd;
        aH = g_SmH + r; aL = g_SmL + r;
    }
    if (MODE == 0) { size_t r = ((size_t)e * Id + n0 + arow) * Hd; bH = g_gwH + r; bL = g_gwL + r; }
    else if (MODE == 1) { size_t r = ((size_t)e * Id + n0 + arow) * Hd; bH = g_uwH + r; bL = g_uwL + r; }
    else if (MODE == 2) { size_t r = (size_t)(n0 + arow) * Hd; bH = g_sgwH + r; bL = g_sgwL + r; }
    else if (MODE == 3) { size_t r = (size_t)(n0 + arow) * Hd; bH = g_suwH + r; bL = g_suwL + r; }
    else if (MODE == 4) { size_t r = ((size_t)e * Hd + n0 + arow) * Id; bH = g_dwH + r; bL = g_dwL + r; }
    else { size_t r = (size_t)(n0 + arow) * ISd; bH = g_sdwH + r; bL = g_sdwL + r; }

    const uint32_t avB = aval ? 16u : 0u;
    const uint32_t vst = (uint32_t)(arow & 7) << 4;
    const uint32_t o0 = ((uint32_t)(sub * 32))      ^ vst;
    const uint32_t o1 = ((uint32_t)(sub * 32 + 16)) ^ vst;
    const uint32_t o2 = ((uint32_t)(64 + sub * 32))      ^ vst;
    const uint32_t o3 = ((uint32_t)(64 + sub * 32 + 16)) ^ vst;
    const uint32_t aDst0 = sb + arow * 128;

    // ---- mma-side ldmatrix bases ----
    const int wm = wid & 3, wn = wid >> 2;
    const uint32_t vA   = (uint32_t)(lane & 7) << 4;
    const uint32_t aLmB = (wm * 32 + (lane & 15)) * 128;
    const uint32_t aLmK = (lane >> 4) * 16;
    const uint32_t bLmB = SM_BOFF + (wn * 64 + ((lane >> 4) & 1) * 8 + (lane & 7)) * 128;
    const uint32_t bCol = ((lane >> 3) & 1) * 16;

    float acc[2][8][4];
    #pragma unroll
    for (int mt = 0; mt < 2; mt++)
        #pragma unroll
        for (int nt = 0; nt < 8; nt++)
            #pragma unroll
            for (int j = 0; j < 4; j++) acc[mt][nt][j] = 0.f;

    auto ISSUE = [&](int kc, int st) {
        const uint32_t aD = aDst0 + st * SM_STAGE;
        const uint32_t bD = aD + SM_BOFF;
        const char* sAH = (const char*)aH + kc * 64 + sub * 32;
        const char* sAL = (const char*)aL + kc * 64 + sub * 32;
        const char* sBH = (const char*)bH + kc * 64 + sub * 32;
        const char* sBL = (const char*)bL + kc * 64 + sub * 32;
        cpa16(aD + o0, sAH, avB);      cpa16(aD + o1, sAH + 16, avB);
        cpa16(aD + o2, sAL, avB);      cpa16(aD + o3, sAL + 16, avB);
        cpa16(bD + o0, sBH, 16u);      cpa16(bD + o1, sBH + 16, 16u);
        cpa16(bD + o2, sBL, 16u);      cpa16(bD + o3, sBL + 16, 16u);
    };

    auto MMA = [&](int st) {
        const uint32_t aS = sb + st * SM_STAGE;
        #pragma unroll
        for (int h = 0; h < 2; h++) {
            uns Ah[2][4], Al[2][4];
            #pragma unroll
            for (int mt = 0; mt < 2; mt++) {
                ldsm4(Ah[mt], aS + aLmB + mt * 2048 + ((h * 32 + aLmK) ^ vA));
                ldsm4(Al[mt], aS + aLmB + mt * 2048 + ((64 + h * 32 + aLmK) ^ vA));
            }
            #pragma unroll
            for (int ntp = 0; ntp < 4; ntp++) {
                uns BH[4], BL[4];
                ldsm4(BH, aS + bLmB + ntp * 2048 + ((h * 32 + bCol) ^ vA));
                ldsm4(BL, aS + bLmB + ntp * 2048 + ((64 + h * 32 + bCol) ^ vA));
                #pragma unroll
                for (int j = 0; j < 2; j++) {
                    const int nt = ntp * 2 + j;
                    #pragma unroll
                    for (int mt = 0; mt < 2; mt++) {
                        mma16816(acc[mt][nt], Ah[mt], BH + j * 2);
                        mma16816(acc[mt][nt], Ah[mt], BL + j * 2);
                        mma16816(acc[mt][nt], Al[mt], BH + j * 2);
                    }
                }
            }
        }
    };

    ISSUE(0, 0); cpcommit();
    for (int kc = 0; kc < NKC; kc++) {
        const int st = kc & 1;
        if (kc + 1 < NKC) { ISSUE(kc + 1, st ^ 1); cpcommit(); cpwait<1>(); }
        else cpwait<0>();
        __syncthreads();
        MMA(st);
        __syncthreads();
    }

    // ---- epilogue ----
    const int rb = wm * 32 + (lane >> 2);
    const int cb = wn * 64 + (lane & 3) * 2;
    #pragma unroll
    for (int mt = 0; mt < 2; mt++) {
        #pragma unroll
        for (int rr = 0; rr < 2; rr++) {
            const int row = rb + mt * 16 + rr * 8;
            if (MODE == 0 || MODE == 1 || MODE == 4) {
                int p = sl[row];
                if (p < 0) continue;
                if (MODE == 0) {
                    float* dst = g_G + (size_t)p * Id + n0 + cb;
                    #pragma unroll
                    for (int nt = 0; nt < 8; nt++)
                        *(float2*)(dst + nt * 8) =
                            make_float2(acc[mt][nt][rr * 2], acc[mt][nt][rr * 2 + 1]);
                } else if (MODE == 1) {
                    float s = g_scores[p];
                    size_t base = (size_t)p * Id + n0 + cb;
                    #pragma unroll
                    for (int nt = 0; nt < 8; nt++) {
                        float2 g2 = *(const float2*)(g_G + base + nt * 8);
                        float u0 = acc[mt][nt][rr * 2], u1 = acc[mt][nt][rr * 2 + 1];
                        float h0 = siluf(s * g2.x) * (s * u0);
                        float h1 = siluf(s * g2.y) * (s * u1);
                        uns phi, plo; split2(h0, h1, phi, plo);
                        *(uns*)(g_HmH + base + nt * 8) = phi;
                        *(uns*)(g_HmL + base + nt * 8) = plo;
                    }
                } else {
                    float* dst = g_Y + (size_t)p * Hd + n0 + cb;
                    #pragma unroll
                    for (int nt = 0; nt < 8; nt++)
                        *(float2*)(dst + nt * 8) =
                            make_float2(acc[mt][nt][rr * 2], acc[mt][nt][rr * 2 + 1]);
                }
            } else {
                const int t = m0 + row;
                if (MODE == 2) {
                    float* dst = g_G + (size_t)t * ISd + n0 + cb;
                    #pragma unroll
                    for (int nt = 0; nt < 8; nt++)
                        *(float2*)(dst + nt * 8) =
                            make_float2(acc[mt][nt][rr * 2], acc[mt][nt][rr * 2 + 1]);
                } else if (MODE == 3) {
                    size_t base = (size_t)t * ISd + n0 + cb;
                    #pragma unroll
                    for (int nt = 0; nt < 8; nt++) {
                        float2 g2 = *(const float2*)(g_G + base + nt * 8);
                        float u0 = acc[mt][nt][rr * 2], u1 = acc[mt][nt][rr * 2 + 1];
                        float h0 = siluf(g2.x) * u0;
                        float h1 = siluf(g2.y) * u1;
                        uns phi, plo; split2(h0, h1, phi, plo);
                        *(uns*)(g_SmH + base + nt * 8) = phi;
                        *(uns*)(g_SmL + base + nt * 8) = plo;
                    }
                } else {
                    size_t col = n0 + cb;
                    const float* y0 = g_Y + (size_t)(2 * t) * Hd + col;
                    const float* y1 = g_Y + (size_t)(2 * t + 1) * Hd + col;
                    float* dst = out + (size_t)t * Hd + col;
                    #pragma unroll
                    for (int nt = 0; nt < 8; nt++) {
                        float2 a = make_float2(acc[mt][nt][rr * 2], acc[mt][nt][rr * 2 + 1]);
                        float2 p0 = *(const float2*)(y0 + nt * 8);
                        float2 p1 = *(const float2*)(y1 + nt * 8);
                        a.x += p0.x + p1.x; a.y += p0.y + p1.y;
                        *(float2*)(dst + nt * 8) = a;
                    }
                }
            }
        }
    }
}

// ---------------- launch ----------------------------------------------------
extern "C" void kernel_launch(void* const* d_in, const int* in_sizes, int n_in,
                              void* d_out, int out_size) {
    const float* x   = (const float*)d_in[0];
    const float* rw  = (const float*)d_in[1];
    const float* gw  = (const float*)d_in[2];
    const float* uw  = (const float*)d_in[3];
    const float* dw  = (const float*)d_in[4];
    const float* sgw = (const float*)d_in[5];
    const float* suw = (const float*)d_in[6];
    const float* sdw = (const float*)d_in[7];
    float* out = (float*)d_out;
    float* logits = out + (size_t)Tn * Hd;

    cudaFuncSetAttribute(k_gemm<0>, cudaFuncAttributeMaxDynamicSharedMemorySize, SMEM_BYTES);
    cudaFuncSetAttribute(k_gemm<1>, cudaFuncAttributeMaxDynamicSharedMemorySize, SMEM_BYTES);
    cudaFuncSetAttribute(k_gemm<2>, cudaFuncAttributeMaxDynamicSharedMemorySize, SMEM_BYTES);
    cudaFuncSetAttribute(k_gemm<3>, cudaFuncAttributeMaxDynamicSharedMemorySize, SMEM_BYTES);
    cudaFuncSetAttribute(k_gemm<4>, cudaFuncAttributeMaxDynamicSharedMemorySize, SMEM_BYTES);
    cudaFuncSetAttribute(k_gemm<5>, cudaFuncAttributeMaxDynamicSharedMemorySize, SMEM_BYTES);

    // resolve device-symbol addresses (host side, graph-capturable: no allocs)
    __nv_bfloat16 *xH, *xL, *gwH, *gwL, *uwH, *uwL, *dwH, *dwL;
    __nv_bfloat16 *sgwH, *sgwL, *suwH, *suwL, *sdwH, *sdwL;
    cudaGetSymbolAddress((void**)&xH, g_xH);   cudaGetSymbolAddress((void**)&xL, g_xL);
    cudaGetSymbolAddress((void**)&gwH, g_gwH); cudaGetSymbolAddress((void**)&gwL, g_gwL);
    cudaGetSymbolAddress((void**)&uwH, g_uwH); cudaGetSymbolAddress((void**)&uwL, g_uwL);
    cudaGetSymbolAddress((void**)&dwH, g_dwH); cudaGetSymbolAddress((void**)&dwL, g_dwL);
    cudaGetSymbolAddress((void**)&sgwH, g_sgwH); cudaGetSymbolAddress((void**)&sgwL, g_sgwL);
    cudaGetSymbolAddress((void**)&suwH, g_suwH); cudaGetSymbolAddress((void**)&suwL, g_suwL);
    cudaGetSymbolAddress((void**)&sdwH, g_sdwH); cudaGetSymbolAddress((void**)&sdwL, g_sdwL);

    k_zero<<<1, 32>>>();
    k_router<<<Tn, 256>>>(x, rw, logits);

    const int nX = Tn * Hd / 4, nW = En * Id * Hd / 4, nS = ISd * Hd / 4;
    k_split<<<nX / 256, 256>>>((const float4*)x,  (uint2*)xH,  (uint2*)xL,  nX);
    k_split<<<nW / 256, 256>>>((const float4*)gw, (uint2*)gwH, (uint2*)gwL, nW);
    k_split<<<nW / 256, 256>>>((const float4*)uw, (uint2*)uwH, (uint2*)uwL, nW);
    k_split<<<nW / 256, 256>>>((const float4*)dw, (uint2*)dwH, (uint2*)dwL, nW);
    k_split<<<nS / 256, 256>>>((const float4*)sgw, (uint2*)sgwH, (uint2*)sgwL, nS);
    k_split<<<nS / 256, 256>>>((const float4*)suw, (uint2*)suwH, (uint2*)suwL, nS);
    k_split<<<nS / 256, 256>>>((const float4*)sdw, (uint2*)sdwH, (uint2*)sdwL, nS);

    k_gemm<0><<<dim3(Tn / BM, Id / BN, En),  NTH, SMEM_BYTES>>>(nullptr);
    k_gemm<1><<<dim3(Tn / BM, Id / BN, En),  NTH, SMEM_BYTES>>>(nullptr);
    k_gemm<4><<<dim3(Tn / BM, Hd / BN, En),  NTH, SMEM_BYTES>>>(nullptr);
    k_gemm<2><<<dim3(Tn / BM, ISd / BN, 1),  NTH, SMEM_BYTES>>>(nullptr);
    k_gemm<3><<<dim3(Tn / BM, ISd / BN, 1),  NTH, SMEM_BYTES>>>(nullptr);
    k_gemm<5><<<dim3(Tn / BM, Hd / BN, 1),   NTH, SMEM_BYTES>>>(out);
}

// round 11
// speedup vs baseline: 3.5233x; 1.0009x over previous
#include <cuda_runtime.h>
#include <cuda_bf16.h>
#include <cstdint>

#define Tn  4096
#define Hd  2048
#define En  8
#define Id  1024
#define ISd 4096

#define BM 128
#define NTH 256

// smem: 3 stages of 32KB (A 16KB + B 16KB each); list after.
#define SM_STAGE 32768
#define SM_BOFF  16384
#define SM_LIST  98304
#define SMEM_BYTES 98816

typedef unsigned uns;

// ---------------- device scratch -------------------------------------------
__device__ int   g_cnt[En];
__device__ int   g_list[En * Tn];
__device__ float g_scores[Tn * 2];
__device__ __nv_bfloat16 g_HmH[(size_t)Tn * 2 * Id];
__device__ __nv_bfloat16 g_HmL[(size_t)Tn * 2 * Id];
__device__ __nv_bfloat16 g_SmH[(size_t)Tn * ISd];
__device__ __nv_bfloat16 g_SmL[(size_t)Tn * ISd];
__device__ float g_Y[(size_t)Tn * 2 * Hd];
// pre-split bf16 operands
__device__ __nv_bfloat16 g_xH[(size_t)Tn * Hd],        g_xL[(size_t)Tn * Hd];
__device__ __nv_bfloat16 g_gwH[(size_t)En * Id * Hd],  g_gwL[(size_t)En * Id * Hd];
__device__ __nv_bfloat16 g_uwH[(size_t)En * Id * Hd],  g_uwL[(size_t)En * Id * Hd];
__device__ __nv_bfloat16 g_dwH[(size_t)En * Hd * Id],  g_dwL[(size_t)En * Hd * Id];
__device__ __nv_bfloat16 g_sgwH[(size_t)ISd * Hd],     g_sgwL[(size_t)ISd * Hd];
__device__ __nv_bfloat16 g_suwH[(size_t)ISd * Hd],     g_suwL[(size_t)ISd * Hd];
__device__ __nv_bfloat16 g_sdwH[(size_t)Hd * ISd],     g_sdwL[(size_t)Hd * ISd];

// ---------------- helpers --------------------------------------------------
__device__ __forceinline__ uint32_t smem_u32(const void* p) {
    uint32_t a;
    asm("{ .reg .u64 t; cvta.to.shared.u64 t, %1; cvt.u32.u64 %0, t; }" : "=r"(a) : "l"(p));
    return a;
}
__device__ __forceinline__ void ldsm4(uns r[4], uint32_t a) {
    asm volatile("ldmatrix.sync.aligned.m8n8.x4.shared.b16 {%0,%1,%2,%3}, [%4];"
        : "=r"(r[0]), "=r"(r[1]), "=r"(r[2]), "=r"(r[3]) : "r"(a));
}
__device__ __forceinline__ void mma16816(float c[4], const uns a[4], const uns b[2]) {
    asm volatile("mma.sync.aligned.m16n8k16.row.col.f32.bf16.bf16.f32 "
        "{%0,%1,%2,%3}, {%4,%5,%6,%7}, {%8,%9}, {%0,%1,%2,%3};"
        : "+f"(c[0]), "+f"(c[1]), "+f"(c[2]), "+f"(c[3])
        : "r"(a[0]), "r"(a[1]), "r"(a[2]), "r"(a[3]), "r"(b[0]), "r"(b[1]));
}
__device__ __forceinline__ void cpa16(uint32_t d, const void* s, uint32_t bytes) {
    asm volatile("cp.async.ca.shared.global [%0], [%1], 16, %2;"
        :: "r"(d), "l"(s), "r"(bytes) : "memory");
}
__device__ __forceinline__ void cpcommit() {
    asm volatile("cp.async.commit_group;" ::: "memory");
}
template<int N> __device__ __forceinline__ void cpwait() {
    asm volatile("cp.async.wait_group %0;" :: "n"(N) : "memory");
}
__device__ __forceinline__ void split2(float a, float b, uns &hi, uns &lo) {
    __nv_bfloat162 h = __floats2bfloat162_rn(a, b);
    float2 hf = __bfloat1622float2(h);
    __nv_bfloat162 l = __floats2bfloat162_rn(a - hf.x, b - hf.y);
    hi = *reinterpret_cast<uns*>(&h);
    lo = *reinterpret_cast<uns*>(&l);
}
__device__ __forceinline__ float siluf(float x) { return x / (1.f + expf(-x)); }

// ---------------- pre-split fp32 -> bf16 hi/lo ------------------------------
__global__ void k_split(const float4* __restrict__ in,
                        uint2* __restrict__ oh, uint2* __restrict__ ol, int n4) {
    int i = blockIdx.x * blockDim.x + threadIdx.x;
    if (i < n4) {
        float4 v = in[i];
        uns h0, l0, h1, l1;
        split2(v.x, v.y, h0, l0);
        split2(v.z, v.w, h1, l1);
        oh[i] = make_uint2(h0, h1);
        ol[i] = make_uint2(l0, l1);
    }
}

// ---------------- router -----------------------------------------------------
__global__ void k_zero() {
    if (threadIdx.x < En) g_cnt[threadIdx.x] = 0;
}

__global__ void k_router(const float* __restrict__ x,
                         const float* __restrict__ rw,
                         float* __restrict__ logits) {
    int t = blockIdx.x;
    int w = threadIdx.x >> 5, lane = threadIdx.x & 31;
    const float* xt = x + (size_t)t * Hd;
    const float* we = rw + (size_t)w * Hd;
    float s = 0.f;
    for (int i = lane * 4; i < Hd; i += 128) {
        float4 xv = *(const float4*)(xt + i);
        float4 wv = *(const float4*)(we + i);
        s += xv.x * wv.x + xv.y * wv.y + xv.z * wv.z + xv.w * wv.w;
    }
    #pragma unroll
    for (int o = 16; o; o >>= 1) s += __shfl_xor_sync(0xffffffffu, s, o);
    __shared__ float lg[En];
    if (!lane) lg[w] = s;
    __syncthreads();
    if (threadIdx.x == 0) {
        #pragma unroll
        for (int e = 0; e < En; e++) logits[(size_t)t * En + e] = lg[e];
        int i0 = 0; float v0 = lg[0];
        #pragma unroll
        for (int e = 1; e < En; e++) if (lg[e] > v0) { v0 = lg[e]; i0 = e; }
        int i1 = -1; float v1 = -3.4e38f;
        #pragma unroll
        for (int e = 0; e < En; e++) if (e != i0 && lg[e] > v1) { v1 = lg[e]; i1 = e; }
        int p0 = t * 2, p1 = t * 2 + 1;
        g_scores[p0] = 1.f / (1.f + expf(-v0));
        g_scores[p1] = 1.f / (1.f + expf(-v1));
        int pos0 = atomicAdd(&g_cnt[i0], 1); g_list[i0 * Tn + pos0] = p0;
        int pos1 = atomicAdd(&g_cnt[i1], 1); g_list[i1 * Tn + pos1] = p1;
    }
}

// ---------------- unified mma.sync GEMM --------------------------------------
// MODE 0: expert gate+up FUSED  A=x(gather)  B=gw|uw interleaved  K=2048 -> HmH/L
// MODE 1: shared gate+up FUSED  A=x          B=sgw|suw interleaved K=2048 -> SmH/L
// MODE 2: expert down           A=Hm         B=dw                  K=1024 -> g_Y
// MODE 3: shared down           A=Sm         B=sdw                 K=4096 -> out (+Y)
// Fused B tile: 128 rows; row r -> matrix j=(r>>3)&1 (0=gate,1=up), 8-group
// i=r>>4, source row n0 + i*8 + (r&7). Then acc[mt][2i]=gate, acc[mt][2i+1]=up
// for the SAME output column in the SAME thread.
template<int MODE>
__global__ __launch_bounds__(NTH, 2) void k_gemm(float* __restrict__ out) {
    extern __shared__ __align__(1024) char smem[];
    const uint32_t sb = smem_u32(smem);
    const int tid = threadIdx.x, wid = tid >> 5, lane = tid & 31;

    constexpr bool EXP = (MODE == 0 || MODE == 2);
    constexpr bool GUP = (MODE == 0 || MODE == 1);
    constexpr int  KT  = GUP ? 2048 : (MODE == 2 ? 1024 : 4096);
    constexpr int  NKC = KT / 32;

    const int e   = EXP ? blockIdx.z : 0;
    const int cnt = EXP ? g_cnt[e] : Tn;
    const int m0  = blockIdx.x * BM;
    if (EXP && m0 >= cnt) return;
    const int n0  = GUP ? blockIdx.y * 64 : blockIdx.y * 128;

    int* sl = (int*)(smem + SM_LIST);
    if (EXP) {
        if (tid < 128) sl[tid] = (m0 + tid < cnt) ? g_list[e * Tn + m0 + tid] : -1;
        __syncthreads();
    }

    // ---- per-thread cp.async source rows (row = tid>>1, sub = tid&1) ----
    const int arow = tid >> 1, sub = tid & 1;
    bool aval = true;
    const __nv_bfloat16 *aH, *aL, *bH, *bL;
    if (MODE == 0) {
        int p = sl[arow]; aval = (p >= 0);
        size_t r = (size_t)(aval ? (p >> 1) : 0) * Hd;
        aH = g_xH + r; aL = g_xL + r;
    } else if (MODE == 1) {
        size_t r = (size_t)(m0 + arow) * Hd;
        aH = g_xH + r; aL = g_xL + r;
    } else if (MODE == 2) {
        int p = sl[arow]; aval = (p >= 0);
        size_t r = (size_t)(aval ? p : 0) * Id;
        aH = g_HmH + r; aL = g_HmL + r;
    } else {
        size_t r = (size_t)(m0 + arow) * ISd;
        aH = g_SmH + r; aL = g_SmL + r;
    }
    if (GUP) {
        const int j = (arow >> 3) & 1;
        const int srow = n0 + (arow >> 4) * 8 + (arow & 7);
        if (MODE == 0) {
            size_t r = ((size_t)e * Id + srow) * Hd;
            bH = (j ? g_uwH : g_gwH) + r;
            bL = (j ? g_uwL : g_gwL) + r;
        } else {
            size_t r = (size_t)srow * Hd;
            bH = (j ? g_suwH : g_sgwH) + r;
            bL = (j ? g_suwL : g_sgwL) + r;
        }
    } else if (MODE == 2) {
        size_t r = ((size_t)e * Hd + n0 + arow) * Id;
        bH = g_dwH + r; bL = g_dwL + r;
    } else {
        size_t r = (size_t)(n0 + arow) * ISd;
        bH = g_sdwH + r; bL = g_sdwL + r;
    }

    const uint32_t avB = aval ? 16u : 0u;
    const uint32_t vst = (uint32_t)(arow & 7) << 4;
    const uint32_t o0 = ((uint32_t)(sub * 32))           ^ vst;
    const uint32_t o1 = ((uint32_t)(sub * 32 + 16))      ^ vst;
    const uint32_t o2 = ((uint32_t)(64 + sub * 32))      ^ vst;
    const uint32_t o3 = ((uint32_t)(64 + sub * 32 + 16)) ^ vst;
    const uint32_t aDst0 = sb + arow * 128;

    // ---- mma-side ldmatrix bases ----
    const int wm = wid & 3, wn = wid >> 2;
    const uint32_t vA   = (uint32_t)(lane & 7) << 4;
    const uint32_t aLmB = (wm * 32 + (lane & 15)) * 128;
    const uint32_t aLmK = (lane >> 4) * 16;
    const uint32_t bLmB = SM_BOFF + (wn * 64 + ((lane >> 4) & 1) * 8 + (lane & 7)) * 128;
    const uint32_t bCol = ((lane >> 3) & 1) * 16;

    float acc[2][8][4];
    #pragma unroll
    for (int mt = 0; mt < 2; mt++)
        #pragma unroll
        for (int nt = 0; nt < 8; nt++)
            #pragma unroll
            for (int j = 0; j < 4; j++) acc[mt][nt][j] = 0.f;

    auto ISSUE = [&](int kc, int st) {
        const uint32_t aD = aDst0 + st * SM_STAGE;
        const uint32_t bD = aD + SM_BOFF;
        const char* sAH = (const char*)aH + kc * 64 + sub * 32;
        const char* sAL = (const char*)aL + kc * 64 + sub * 32;
        const char* sBH = (const char*)bH + kc * 64 + sub * 32;
        const char* sBL = (const char*)bL + kc * 64 + sub * 32;
        cpa16(aD + o0, sAH, avB);      cpa16(aD + o1, sAH + 16, avB);
        cpa16(aD + o2, sAL, avB);      cpa16(aD + o3, sAL + 16, avB);
        cpa16(bD + o0, sBH, 16u);      cpa16(bD + o1, sBH + 16, 16u);
        cpa16(bD + o2, sBL, 16u);      cpa16(bD + o3, sBL + 16, 16u);
        cpcommit();
    };

    auto MMA = [&](int st) {
        const uint32_t aS = sb + st * SM_STAGE;
        #pragma unroll
        for (int h = 0; h < 2; h++) {
            uns Ah[2][4], Al[2][4];
            #pragma unroll
            for (int mt = 0; mt < 2; mt++) {
                ldsm4(Ah[mt], aS + aLmB + mt * 2048 + ((h * 32 + aLmK) ^ vA));
                ldsm4(Al[mt], aS + aLmB + mt * 2048 + ((64 + h * 32 + aLmK) ^ vA));
            }
            #pragma unroll
            for (int ntp = 0; ntp < 4; ntp++) {
                uns BH[4], BL[4];
                ldsm4(BH, aS + bLmB + ntp * 2048 + ((h * 32 + bCol) ^ vA));
                ldsm4(BL, aS + bLmB + ntp * 2048 + ((64 + h * 32 + bCol) ^ vA));
                #pragma unroll
                for (int j = 0; j < 2; j++) {
                    const int nt = ntp * 2 + j;
                    #pragma unroll
                    for (int mt = 0; mt < 2; mt++) {
                        mma16816(acc[mt][nt], Ah[mt], BH + j * 2);
                        mma16816(acc[mt][nt], Ah[mt], BL + j * 2);
                        mma16816(acc[mt][nt], Al[mt], BH + j * 2);
                    }
                }
            }
        }
    };

    // 3-stage pipeline, ONE barrier per chunk.
    ISSUE(0, 0);
    ISSUE(1, 1);
    for (int kc = 0; kc < NKC; kc++) {
        const int st = kc % 3;
        if (kc + 1 < NKC) cpwait<1>(); else cpwait<0>();
        __syncthreads();
        if (kc + 2 < NKC) ISSUE(kc + 2, (kc + 2) % 3);
        MMA(st);
    }

    // ---- epilogue ----
    const int rb = wm * 32 + (lane >> 2);
    const int cq = (lane & 3) * 2;
    #pragma unroll
    for (int mt = 0; mt < 2; mt++) {
        #pragma unroll
        for (int rr = 0; rr < 2; rr++) {
            const int row = rb + mt * 16 + rr * 8;
            if (GUP) {
                float s; size_t base;
                if (MODE == 0) {
                    int p = sl[row];
                    if (p < 0) continue;
                    s = g_scores[p];
                    base = (size_t)p * Id;
                } else {
                    s = 1.f;
                    base = (size_t)(m0 + row) * ISd;
                }
                #pragma unroll
                for (int i = 0; i < 4; i++) {
                    float g0 = acc[mt][2 * i][rr * 2],     g1 = acc[mt][2 * i][rr * 2 + 1];
                    float u0 = acc[mt][2 * i + 1][rr * 2], u1 = acc[mt][2 * i + 1][rr * 2 + 1];
                    float h0, h1;
                    if (MODE == 0) { h0 = siluf(s * g0) * (s * u0); h1 = siluf(s * g1) * (s * u1); }
                    else           { h0 = siluf(g0) * u0;           h1 = siluf(g1) * u1; }
                    uns phi, plo; split2(h0, h1, phi, plo);
                    size_t idx = base + (size_t)(n0 + (wn * 4 + i) * 8 + cq);
                    if (MODE == 0) {
                        *(uns*)(g_HmH + idx) = phi; *(uns*)(g_HmL + idx) = plo;
                    } else {
                        *(uns*)(g_SmH + idx) = phi; *(uns*)(g_SmL + idx) = plo;
                    }
                }
            } else if (MODE == 2) {
                int p = sl[row];
                if (p < 0) continue;
                float* dst = g_Y + (size_t)p * Hd + n0 + wn * 64 + cq;
                #pragma unroll
                for (int nt = 0; nt < 8; nt++)
                    *(float2*)(dst + nt * 8) =
                        make_float2(acc[mt][nt][rr * 2], acc[mt][nt][rr * 2 + 1]);
            } else {
                const int t = m0 + row;
                size_t col = (size_t)(n0 + wn * 64 + cq);
                const float* y0 = g_Y + (size_t)(2 * t) * Hd + col;
                const float* y1 = g_Y + (size_t)(2 * t + 1) * Hd + col;
                float* dst = out + (size_t)t * Hd + col;
                #pragma unroll
                for (int nt = 0; nt < 8; nt++) {
                    float2 a = make_float2(acc[mt][nt][rr * 2], acc[mt][nt][rr * 2 + 1]);
                    float2 p0 = *(const float2*)(y0 + nt * 8);
                    float2 p1 = *(const float2*)(y1 + nt * 8);
                    a.x += p0.x + p1.x; a.y += p0.y + p1.y;
                    *(float2*)(dst + nt * 8) = a;
                }
            }
        }
    }
}

// ---------------- launch ----------------------------------------------------
extern "C" void kernel_launch(void* const* d_in, const int* in_sizes, int n_in,
                              void* d_out, int out_size) {
    const float* x   = (const float*)d_in[0];
    const float* rw  = (const float*)d_in[1];
    const float* gw  = (const float*)d_in[2];
    const float* uw  = (const float*)d_in[3];
    const float* dw  = (const float*)d_in[4];
    const float* sgw = (const float*)d_in[5];
    const float* suw = (const float*)d_in[6];
    const float* sdw = (const float*)d_in[7];
    float* out = (float*)d_out;
    float* logits = out + (size_t)Tn * Hd;

    cudaFuncSetAttribute(k_gemm<0>, cudaFuncAttributeMaxDynamicSharedMemorySize, SMEM_BYTES);
    cudaFuncSetAttribute(k_gemm<1>, cudaFuncAttributeMaxDynamicSharedMemorySize, SMEM_BYTES);
    cudaFuncSetAttribute(k_gemm<2>, cudaFuncAttributeMaxDynamicSharedMemorySize, SMEM_BYTES);
    cudaFuncSetAttribute(k_gemm<3>, cudaFuncAttributeMaxDynamicSharedMemorySize, SMEM_BYTES);

    __nv_bfloat16 *xH, *xL, *gwH, *gwL, *uwH, *uwL, *dwH, *dwL;
    __nv_bfloat16 *sgwH, *sgwL, *suwH, *suwL, *sdwH, *sdwL;
    cudaGetSymbolAddress((void**)&xH, g_xH);   cudaGetSymbolAddress((void**)&xL, g_xL);
    cudaGetSymbolAddress((void**)&gwH, g_gwH); cudaGetSymbolAddress((void**)&gwL, g_gwL);
    cudaGetSymbolAddress((void**)&uwH, g_uwH); cudaGetSymbolAddress((void**)&uwL, g_uwL);
    cudaGetSymbolAddress((void**)&dwH, g_dwH); cudaGetSymbolAddress((void**)&dwL, g_dwL);
    cudaGetSymbolAddress((void**)&sgwH, g_sgwH); cudaGetSymbolAddress((void**)&sgwL, g_sgwL);
    cudaGetSymbolAddress((void**)&suwH, g_suwH); cudaGetSymbolAddress((void**)&suwL, g_suwL);
    cudaGetSymbolAddress((void**)&sdwH, g_sdwH); cudaGetSymbolAddress((void**)&sdwL, g_sdwL);

    k_zero<<<1, 32>>>();
    k_router<<<Tn, 256>>>(x, rw, logits);

    const int nX = Tn * Hd / 4, nW = En * Id * Hd / 4, nS = ISd * Hd / 4;
    k_split<<<nX / 256, 256>>>((const float4*)x,  (uint2*)xH,  (uint2*)xL,  nX);
    k_split<<<nW / 256, 256>>>((const float4*)gw, (uint2*)gwH, (uint2*)gwL, nW);
    k_split<<<nW / 256, 256>>>((const float4*)uw, (uint2*)uwH, (uint2*)uwL, nW);
    k_split<<<nW / 256, 256>>>((const float4*)dw, (uint2*)dwH, (uint2*)dwL, nW);
    k_split<<<nS / 256, 256>>>((const float4*)sgw, (uint2*)sgwH, (uint2*)sgwL, nS);
    k_split<<<nS / 256, 256>>>((const float4*)suw, (uint2*)suwH, (uint2*)suwL, nS);
    k_split<<<nS / 256, 256>>>((const float4*)sdw, (uint2*)sdwH, (uint2*)sdwL, nS);

    k_gemm<0><<<dim3(Tn / BM, Id / 64, En),  NTH, SMEM_BYTES>>>(nullptr);
    k_gemm<2><<<dim3(Tn / BM, Hd / 128, En), NTH, SMEM_BYTES>>>(nullptr);
    k_gemm<1><<<dim3(Tn / BM, ISd / 64, 1),  NTH, SMEM_BYTES>>>(nullptr);
    k_gemm<3><<<dim3(Tn / BM, Hd / 128, 1),  NTH, SMEM_BYTES>>>(out);
}

// round 12
// speedup vs baseline: 4.8698x; 1.3822x over previous
#include <cuda_runtime.h>
#include <cuda_fp16.h>
#include <cstdint>

#define Tn  4096
#define Hd  2048
#define En  8
#define Id  1024
#define ISd 4096

#define BM 128
#define NTH 256

// smem: 4 stages of 24KB (A 16KB hi|lo fp16 + B 8KB fp16); list after.
#define SM_STAGE 24576
#define SM_BOFF  16384
#define SM_LIST  98304
#define SMEM_BYTES 98816

typedef unsigned uns;

// ---------------- device scratch -------------------------------------------
__device__ int   g_cnt[En];
__device__ int   g_list[En * Tn];
__device__ float g_scores[Tn * 2];
__device__ __half g_HmH[(size_t)Tn * 2 * Id];
__device__ __half g_HmL[(size_t)Tn * 2 * Id];
__device__ __half g_SmH[(size_t)Tn * ISd];
__device__ __half g_SmL[(size_t)Tn * ISd];
__device__ float g_Y[(size_t)Tn * 2 * Hd];
// pre-split activations (hi/lo fp16), pre-converted weights (single fp16)
__device__ __half g_xH[(size_t)Tn * Hd],  g_xL[(size_t)Tn * Hd];
__device__ __half g_gwF[(size_t)En * Id * Hd];
__device__ __half g_uwF[(size_t)En * Id * Hd];
__device__ __half g_dwF[(size_t)En * Hd * Id];
__device__ __half g_sgwF[(size_t)ISd * Hd];
__device__ __half g_suwF[(size_t)ISd * Hd];
__device__ __half g_sdwF[(size_t)Hd * ISd];

// ---------------- helpers --------------------------------------------------
__device__ __forceinline__ uint32_t smem_u32(const void* p) {
    uint32_t a;
    asm("{ .reg .u64 t; cvta.to.shared.u64 t, %1; cvt.u32.u64 %0, t; }" : "=r"(a) : "l"(p));
    return a;
}
__device__ __forceinline__ void ldsm4(uns r[4], uint32_t a) {
    asm volatile("ldmatrix.sync.aligned.m8n8.x4.shared.b16 {%0,%1,%2,%3}, [%4];"
        : "=r"(r[0]), "=r"(r[1]), "=r"(r[2]), "=r"(r[3]) : "r"(a));
}
__device__ __forceinline__ void mma16816(float c[4], const uns a[4], const uns b[2]) {
    asm volatile("mma.sync.aligned.m16n8k16.row.col.f32.f16.f16.f32 "
        "{%0,%1,%2,%3}, {%4,%5,%6,%7}, {%8,%9}, {%0,%1,%2,%3};"
        : "+f"(c[0]), "+f"(c[1]), "+f"(c[2]), "+f"(c[3])
        : "r"(a[0]), "r"(a[1]), "r"(a[2]), "r"(a[3]), "r"(b[0]), "r"(b[1]));
}
__device__ __forceinline__ void cpa16(uint32_t d, const void* s, uint32_t bytes) {
    asm volatile("cp.async.ca.shared.global [%0], [%1], 16, %2;"
        :: "r"(d), "l"(s), "r"(bytes) : "memory");
}
__device__ __forceinline__ void cpcommit() {
    asm volatile("cp.async.commit_group;" ::: "memory");
}
template<int N> __device__ __forceinline__ void cpwait() {
    asm volatile("cp.async.wait_group %0;" :: "n"(N) : "memory");
}
__device__ __forceinline__ void split2h(float a, float b, uns &hi, uns &lo) {
    __half2 h = __floats2half2_rn(a, b);
    float2 hf = __half22float2(h);
    __half2 l = __floats2half2_rn(a - hf.x, b - hf.y);
    hi = *reinterpret_cast<uns*>(&h);
    lo = *reinterpret_cast<uns*>(&l);
}
__device__ __forceinline__ float siluf(float x) { return x / (1.f + expf(-x)); }

// ---------------- pre-split / pre-convert kernels ---------------------------
__global__ void k_splitX(const float4* __restrict__ in,
                         uint2* __restrict__ oh, uint2* __restrict__ ol, int n4) {
    int i = blockIdx.x * blockDim.x + threadIdx.x;
    if (i < n4) {
        float4 v = in[i];
        uns h0, l0, h1, l1;
        split2h(v.x, v.y, h0, l0);
        split2h(v.z, v.w, h1, l1);
        oh[i] = make_uint2(h0, h1);
        ol[i] = make_uint2(l0, l1);
    }
}
__global__ void k_splitW(const float4* __restrict__ in, uint2* __restrict__ o, int n4) {
    int i = blockIdx.x * blockDim.x + threadIdx.x;
    if (i < n4) {
        float4 v = in[i];
        __half2 a = __floats2half2_rn(v.x, v.y);
        __half2 b = __floats2half2_rn(v.z, v.w);
        o[i] = make_uint2(*reinterpret_cast<uns*>(&a), *reinterpret_cast<uns*>(&b));
    }
}

// ---------------- router -----------------------------------------------------
__global__ void k_zero() {
    if (threadIdx.x < En) g_cnt[threadIdx.x] = 0;
}

__global__ void k_router(const float* __restrict__ x,
                         const float* __restrict__ rw,
                         float* __restrict__ logits) {
    int t = blockIdx.x;
    int w = threadIdx.x >> 5, lane = threadIdx.x & 31;
    const float* xt = x + (size_t)t * Hd;
    const float* we = rw + (size_t)w * Hd;
    float s = 0.f;
    for (int i = lane * 4; i < Hd; i += 128) {
        float4 xv = *(const float4*)(xt + i);
        float4 wv = *(const float4*)(we + i);
        s += xv.x * wv.x + xv.y * wv.y + xv.z * wv.z + xv.w * wv.w;
    }
    #pragma unroll
    for (int o = 16; o; o >>= 1) s += __shfl_xor_sync(0xffffffffu, s, o);
    __shared__ float lg[En];
    if (!lane) lg[w] = s;
    __syncthreads();
    if (threadIdx.x == 0) {
        #pragma unroll
        for (int e = 0; e < En; e++) logits[(size_t)t * En + e] = lg[e];
        int i0 = 0; float v0 = lg[0];
        #pragma unroll
        for (int e = 1; e < En; e++) if (lg[e] > v0) { v0 = lg[e]; i0 = e; }
        int i1 = -1; float v1 = -3.4e38f;
        #pragma unroll
        for (int e = 0; e < En; e++) if (e != i0 && lg[e] > v1) { v1 = lg[e]; i1 = e; }
        int p0 = t * 2, p1 = t * 2 + 1;
        g_scores[p0] = 1.f / (1.f + expf(-v0));
        g_scores[p1] = 1.f / (1.f + expf(-v1));
        int pos0 = atomicAdd(&g_cnt[i0], 1); g_list[i0 * Tn + pos0] = p0;
        int pos1 = atomicAdd(&g_cnt[i1], 1); g_list[i1 * Tn + pos1] = p1;
    }
}

// ---------------- unified mma.sync GEMM (2-MMA fp16 asymmetric split) -------
// MODE 0: expert gate+up FUSED  A=x(gather)  B=gw|uw interleaved   K=2048 -> HmH/L
// MODE 1: shared gate+up FUSED  A=x          B=sgw|suw interleaved K=2048 -> SmH/L
// MODE 2: expert down           A=Hm         B=dw                  K=1024 -> g_Y
// MODE 3: shared down           A=Sm         B=sdw                 K=4096 -> out (+Y)
template<int MODE>
__global__ __launch_bounds__(NTH, 2) void k_gemm(float* __restrict__ out) {
    extern __shared__ __align__(1024) char smem[];
    const uint32_t sb = smem_u32(smem);
    const int tid = threadIdx.x, wid = tid >> 5, lane = tid & 31;

    constexpr bool EXP = (MODE == 0 || MODE == 2);
    constexpr bool GUP = (MODE == 0 || MODE == 1);
    constexpr int  KT  = GUP ? 2048 : (MODE == 2 ? 1024 : 4096);
    constexpr int  NKC = KT / 32;

    const int e   = EXP ? blockIdx.z : 0;
    const int cnt = EXP ? g_cnt[e] : Tn;
    const int m0  = blockIdx.x * BM;
    if (EXP && m0 >= cnt) return;
    const int n0  = GUP ? blockIdx.y * 64 : blockIdx.y * 128;

    int* sl = (int*)(smem + SM_LIST);
    if (EXP) {
        if (tid < 128) sl[tid] = (m0 + tid < cnt) ? g_list[e * Tn + m0 + tid] : -1;
        __syncthreads();
    }

    // ---- per-thread cp.async source rows (row = tid>>1, sub = tid&1) ----
    const int arow = tid >> 1, sub = tid & 1;
    bool aval = true;
    const __half *aH, *aL, *bF;
    if (MODE == 0) {
        int p = sl[arow]; aval = (p >= 0);
        size_t r = (size_t)(aval ? (p >> 1) : 0) * Hd;
        aH = g_xH + r; aL = g_xL + r;
    } else if (MODE == 1) {
        size_t r = (size_t)(m0 + arow) * Hd;
        aH = g_xH + r; aL = g_xL + r;
    } else if (MODE == 2) {
        int p = sl[arow]; aval = (p >= 0);
        size_t r = (size_t)(aval ? p : 0) * Id;
        aH = g_HmH + r; aL = g_HmL + r;
    } else {
        size_t r = (size_t)(m0 + arow) * ISd;
        aH = g_SmH + r; aL = g_SmL + r;
    }
    if (GUP) {
        const int j = (arow >> 3) & 1;
        const int srow = n0 + (arow >> 4) * 8 + (arow & 7);
        if (MODE == 0) bF = (j ? g_uwF : g_gwF) + ((size_t)e * Id + srow) * Hd;
        else           bF = (j ? g_suwF : g_sgwF) + (size_t)srow * Hd;
    } else if (MODE == 2) {
        bF = g_dwF + ((size_t)e * Hd + n0 + arow) * Id;
    } else {
        bF = g_sdwF + (size_t)(n0 + arow) * ISd;
    }

    const uint32_t avB = aval ? 16u : 0u;
    // A store offsets (128B rows, swizzle on row&7)
    const uint32_t vst = (uint32_t)(arow & 7) << 4;
    const uint32_t o0 = ((uint32_t)(sub * 32))           ^ vst;
    const uint32_t o1 = ((uint32_t)(sub * 32 + 16))      ^ vst;
    const uint32_t o2 = ((uint32_t)(64 + sub * 32))      ^ vst;
    const uint32_t o3 = ((uint32_t)(64 + sub * 32 + 16)) ^ vst;
    const uint32_t aDst0 = sb + arow * 128;
    // B store offsets (64B rows, swizzle on (row>>1)&3)
    const uint32_t bsw = (uint32_t)((arow >> 1) & 3) << 4;
    const uint32_t b0 = ((uint32_t)(sub * 32))      ^ bsw;
    const uint32_t b1 = ((uint32_t)(sub * 32 + 16)) ^ bsw;
    const uint32_t bDst0 = sb + SM_BOFF + arow * 64;

    // ---- mma-side ldmatrix bases ----
    const int wm = wid & 3, wn = wid >> 2;
    const uint32_t vA   = (uint32_t)(lane & 7) << 4;
    const uint32_t aLmB = (wm * 32 + (lane & 15)) * 128;
    const uint32_t aLmK = (lane >> 4) * 16;
    const uint32_t bLmRow = wn * 64 + ((lane >> 4) & 1) * 8 + (lane & 7);
    const uint32_t bLmB = SM_BOFF + bLmRow * 64;
    const uint32_t bswL = (uint32_t)((bLmRow >> 1) & 3) << 4;
    const uint32_t bCol = ((lane >> 3) & 1) * 16;

    float acc[2][8][4];
    #pragma unroll
    for (int mt = 0; mt < 2; mt++)
        #pragma unroll
        for (int nt = 0; nt < 8; nt++)
            #pragma unroll
            for (int j = 0; j < 4; j++) acc[mt][nt][j] = 0.f;

    auto ISSUE = [&](int kc, int st) {
        const uint32_t aD = aDst0 + st * SM_STAGE;
        const uint32_t bD = bDst0 + st * SM_STAGE;
        const char* sAH = (const char*)aH + kc * 64 + sub * 32;
        const char* sAL = (const char*)aL + kc * 64 + sub * 32;
        const char* sB  = (const char*)bF + kc * 64 + sub * 32;
        cpa16(aD + o0, sAH, avB);      cpa16(aD + o1, sAH + 16, avB);
        cpa16(aD + o2, sAL, avB);      cpa16(aD + o3, sAL + 16, avB);
        cpa16(bD + b0, sB, 16u);       cpa16(bD + b1, sB + 16, 16u);
        cpcommit();
    };

    auto MMA = [&](int st) {
        const uint32_t aS = sb + st * SM_STAGE;
        #pragma unroll
        for (int h = 0; h < 2; h++) {
            uns Ah[2][4], Al[2][4];
            #pragma unroll
            for (int mt = 0; mt < 2; mt++) {
                ldsm4(Ah[mt], aS + aLmB + mt * 2048 + ((h * 32 + aLmK) ^ vA));
                ldsm4(Al[mt], aS + aLmB + mt * 2048 + ((64 + h * 32 + aLmK) ^ vA));
            }
            #pragma unroll
            for (int ntp = 0; ntp < 4; ntp++) {
                uns B4[4];
                ldsm4(B4, aS + bLmB + ntp * 1024 + ((h * 32 + bCol) ^ bswL));
                #pragma unroll
                for (int j = 0; j < 2; j++) {
                    const int nt = ntp * 2 + j;
                    #pragma unroll
                    for (int mt = 0; mt < 2; mt++) {
                        mma16816(acc[mt][nt], Ah[mt], B4 + j * 2);
                        mma16816(acc[mt][nt], Al[mt], B4 + j * 2);
                    }
                }
            }
        }
    };

    // 4-stage pipeline, one barrier per chunk, 3 chunks of latency buffer.
    ISSUE(0, 0); ISSUE(1, 1); ISSUE(2, 2);
    for (int kc = 0; kc < NKC; kc++) {
        if (kc + 1 >= NKC)      cpwait<0>();
        else if (kc + 2 >= NKC) cpwait<1>();
        else                    cpwait<2>();
        __syncthreads();
        if (kc + 3 < NKC) ISSUE(kc + 3, (kc + 3) & 3);
        MMA(kc & 3);
    }

    // ---- epilogue ----
    const int rb = wm * 32 + (lane >> 2);
    const int cq = (lane & 3) * 2;
    #pragma unroll
    for (int mt = 0; mt < 2; mt++) {
        #pragma unroll
        for (int rr = 0; rr < 2; rr++) {
            const int row = rb + mt * 16 + rr * 8;
            if (GUP) {
                float s; size_t base;
                if (MODE == 0) {
                    int p = sl[row];
                    if (p < 0) continue;
                    s = g_scores[p];
                    base = (size_t)p * Id;
                } else {
                    s = 1.f;
                    base = (size_t)(m0 + row) * ISd;
                }
                #pragma unroll
                for (int i = 0; i < 4; i++) {
                    float g0 = acc[mt][2 * i][rr * 2],     g1 = acc[mt][2 * i][rr * 2 + 1];
                    float u0 = acc[mt][2 * i + 1][rr * 2], u1 = acc[mt][2 * i + 1][rr * 2 + 1];
                    float h0, h1;
                    if (MODE == 0) { h0 = siluf(s * g0) * (s * u0); h1 = siluf(s * g1) * (s * u1); }
                    else           { h0 = siluf(g0) * u0;           h1 = siluf(g1) * u1; }
                    uns phi, plo; split2h(h0, h1, phi, plo);
                    size_t idx = base + (size_t)(n0 + (wn * 4 + i) * 8 + cq);
                    if (MODE == 0) {
                        *(uns*)(g_HmH + idx) = phi; *(uns*)(g_HmL + idx) = plo;
                    } else {
                        *(uns*)(g_SmH + idx) = phi; *(uns*)(g_SmL + idx) = plo;
                    }
                }
            } else if (MODE == 2) {
                int p = sl[row];
                if (p < 0) continue;
                float* dst = g_Y + (size_t)p * Hd + n0 + wn * 64 + cq;
                #pragma unroll
                for (int nt = 0; nt < 8; nt++)
                    *(float2*)(dst + nt * 8) =
                        make_float2(acc[mt][nt][rr * 2], acc[mt][nt][rr * 2 + 1]);
            } else {
                const int t = m0 + row;
                size_t col = (size_t)(n0 + wn * 64 + cq);
                const float* y0 = g_Y + (size_t)(2 * t) * Hd + col;
                const float* y1 = g_Y + (size_t)(2 * t + 1) * Hd + col;
                float* dst = out + (size_t)t * Hd + col;
                #pragma unroll
                for (int nt = 0; nt < 8; nt++) {
                    float2 a = make_float2(acc[mt][nt][rr * 2], acc[mt][nt][rr * 2 + 1]);
                    float2 p0 = *(const float2*)(y0 + nt * 8);
                    float2 p1 = *(const float2*)(y1 + nt * 8);
                    a.x += p0.x + p1.x; a.y += p0.y + p1.y;
                    *(float2*)(dst + nt * 8) = a;
                }
            }
        }
    }
}

// ---------------- launch ----------------------------------------------------
extern "C" void kernel_launch(void* const* d_in, const int* in_sizes, int n_in,
                              void* d_out, int out_size) {
    const float* x   = (const float*)d_in[0];
    const float* rw  = (const float*)d_in[1];
    const float* gw  = (const float*)d_in[2];
    const float* uw  = (const float*)d_in[3];
    const float* dw  = (const float*)d_in[4];
    const float* sgw = (const float*)d_in[5];
    const float* suw = (const float*)d_in[6];
    const float* sdw = (const float*)d_in[7];
    float* out = (float*)d_out;
    float* logits = out + (size_t)Tn * Hd;

    cudaFuncSetAttribute(k_gemm<0>, cudaFuncAttributeMaxDynamicSharedMemorySize, SMEM_BYTES);
    cudaFuncSetAttribute(k_gemm<1>, cudaFuncAttributeMaxDynamicSharedMemorySize, SMEM_BYTES);
    cudaFuncSetAttribute(k_gemm<2>, cudaFuncAttributeMaxDynamicSharedMemorySize, SMEM_BYTES);
    cudaFuncSetAttribute(k_gemm<3>, cudaFuncAttributeMaxDynamicSharedMemorySize, SMEM_BYTES);

    __half *xH, *xL, *gwF, *uwF, *dwF, *sgwF, *suwF, *sdwF;
    cudaGetSymbolAddress((void**)&xH, g_xH);   cudaGetSymbolAddress((void**)&xL, g_xL);
    cudaGetSymbolAddress((void**)&gwF, g_gwF); cudaGetSymbolAddress((void**)&uwF, g_uwF);
    cudaGetSymbolAddress((void**)&dwF, g_dwF);
    cudaGetSymbolAddress((void**)&sgwF, g_sgwF); cudaGetSymbolAddress((void**)&suwF, g_suwF);
    cudaGetSymbolAddress((void**)&sdwF, g_sdwF);

    k_zero<<<1, 32>>>();
    k_router<<<Tn, 256>>>(x, rw, logits);

    const int nX = Tn * Hd / 4, nW = En * Id * Hd / 4, nS = ISd * Hd / 4;
    k_splitX<<<nX / 256, 256>>>((const float4*)x, (uint2*)xH, (uint2*)xL, nX);
    k_splitW<<<nW / 256, 256>>>((const float4*)gw,  (uint2*)gwF,  nW);
    k_splitW<<<nW / 256, 256>>>((const float4*)uw,  (uint2*)uwF,  nW);
    k_splitW<<<nW / 256, 256>>>((const float4*)dw,  (uint2*)dwF,  nW);
    k_splitW<<<nS / 256, 256>>>((const float4*)sgw, (uint2*)sgwF, nS);
    k_splitW<<<nS / 256, 256>>>((const float4*)suw, (uint2*)suwF, nS);
    k_splitW<<<nS / 256, 256>>>((const float4*)sdw, (uint2*)sdwF, nS);

    k_gemm<0><<<dim3(Tn / BM, Id / 64, En),  NTH, SMEM_BYTES>>>(nullptr);
    k_gemm<2><<<dim3(Tn / BM, Hd / 128, En), NTH, SMEM_BYTES>>>(nullptr);
    k_gemm<1><<<dim3(Tn / BM, ISd / 64, 1),  NTH, SMEM_BYTES>>>(nullptr);
    k_gemm<3><<<dim3(Tn / BM, Hd / 128, 1),  NTH, SMEM_BYTES>>>(out);
}

// round 13
// speedup vs baseline: 7.8271x; 1.6073x over previous
#include <cuda_runtime.h>
#include <cuda_fp16.h>
#include <cstdint>

#define Tn  4096
#define Hd  2048
#define En  8
#define Id  1024
#define ISd 4096

#define BM 128
#define NTH 256

// smem: 4 stages of 16KB (A 8KB fp16 + B 8KB fp16); list after.
#define SM_STAGE 16384
#define SM_BOFF  8192
#define SM_LIST  65536
#define SMEM_BYTES 66048

typedef unsigned uns;

// ---------------- device scratch -------------------------------------------
__device__ int   g_cnt[En];
__device__ int   g_list[En * Tn];
__device__ float g_scores[Tn * 2];
__device__ __half g_Hm[(size_t)Tn * 2 * Id];
__device__ __half g_Sm[(size_t)Tn * ISd];
__device__ float g_Y[(size_t)Tn * 2 * Hd];
// pre-converted fp16 operands
__device__ __half g_xF[(size_t)Tn * Hd];
__device__ __half g_gwF[(size_t)En * Id * Hd];
__device__ __half g_uwF[(size_t)En * Id * Hd];
__device__ __half g_dwF[(size_t)En * Hd * Id];
__device__ __half g_sgwF[(size_t)ISd * Hd];
__device__ __half g_suwF[(size_t)ISd * Hd];
__device__ __half g_sdwF[(size_t)Hd * ISd];

// ---------------- helpers --------------------------------------------------
__device__ __forceinline__ uint32_t smem_u32(const void* p) {
    uint32_t a;
    asm("{ .reg .u64 t; cvta.to.shared.u64 t, %1; cvt.u32.u64 %0, t; }" : "=r"(a) : "l"(p));
    return a;
}
__device__ __forceinline__ void ldsm4(uns r[4], uint32_t a) {
    asm volatile("ldmatrix.sync.aligned.m8n8.x4.shared.b16 {%0,%1,%2,%3}, [%4];"
        : "=r"(r[0]), "=r"(r[1]), "=r"(r[2]), "=r"(r[3]) : "r"(a));
}
__device__ __forceinline__ void mma16816(float c[4], const uns a[4], const uns b[2]) {
    asm volatile("mma.sync.aligned.m16n8k16.row.col.f32.f16.f16.f32 "
        "{%0,%1,%2,%3}, {%4,%5,%6,%7}, {%8,%9}, {%0,%1,%2,%3};"
        : "+f"(c[0]), "+f"(c[1]), "+f"(c[2]), "+f"(c[3])
        : "r"(a[0]), "r"(a[1]), "r"(a[2]), "r"(a[3]), "r"(b[0]), "r"(b[1]));
}
__device__ __forceinline__ void cpa16(uint32_t d, const void* s, uint32_t bytes) {
    asm volatile("cp.async.ca.shared.global [%0], [%1], 16, %2;"
        :: "r"(d), "l"(s), "r"(bytes) : "memory");
}
__device__ __forceinline__ void cpcommit() {
    asm volatile("cp.async.commit_group;" ::: "memory");
}
template<int N> __device__ __forceinline__ void cpwait() {
    asm volatile("cp.async.wait_group %0;" :: "n"(N) : "memory");
}
__device__ __forceinline__ float siluf(float x) { return x / (1.f + expf(-x)); }

// ---------------- pre-convert fp32 -> fp16 ----------------------------------
__global__ void k_cvt(const float4* __restrict__ in, uint2* __restrict__ o, int n4) {
    int i = blockIdx.x * blockDim.x + threadIdx.x;
    if (i < n4) {
        float4 v = in[i];
        __half2 a = __floats2half2_rn(v.x, v.y);
        __half2 b = __floats2half2_rn(v.z, v.w);
        o[i] = make_uint2(*reinterpret_cast<uns*>(&a), *reinterpret_cast<uns*>(&b));
    }
}

// ---------------- router -----------------------------------------------------
__global__ void k_zero() {
    if (threadIdx.x < En) g_cnt[threadIdx.x] = 0;
}

__global__ void k_router(const float* __restrict__ x,
                         const float* __restrict__ rw,
                         float* __restrict__ logits) {
    int t = blockIdx.x;
    int w = threadIdx.x >> 5, lane = threadIdx.x & 31;
    const float* xt = x + (size_t)t * Hd;
    const float* we = rw + (size_t)w * Hd;
    float s = 0.f;
    for (int i = lane * 4; i < Hd; i += 128) {
        float4 xv = *(const float4*)(xt + i);
        float4 wv = *(const float4*)(we + i);
        s += xv.x * wv.x + xv.y * wv.y + xv.z * wv.z + xv.w * wv.w;
    }
    #pragma unroll
    for (int o = 16; o; o >>= 1) s += __shfl_xor_sync(0xffffffffu, s, o);
    __shared__ float lg[En];
    if (!lane) lg[w] = s;
    __syncthreads();
    if (threadIdx.x == 0) {
        #pragma unroll
        for (int e = 0; e < En; e++) logits[(size_t)t * En + e] = lg[e];
        int i0 = 0; float v0 = lg[0];
        #pragma unroll
        for (int e = 1; e < En; e++) if (lg[e] > v0) { v0 = lg[e]; i0 = e; }
        int i1 = -1; float v1 = -3.4e38f;
        #pragma unroll
        for (int e = 0; e < En; e++) if (e != i0 && lg[e] > v1) { v1 = lg[e]; i1 = e; }
        int p0 = t * 2, p1 = t * 2 + 1;
        g_scores[p0] = 1.f / (1.f + expf(-v0));
        g_scores[p1] = 1.f / (1.f + expf(-v1));
        int pos0 = atomicAdd(&g_cnt[i0], 1); g_list[i0 * Tn + pos0] = p0;
        int pos1 = atomicAdd(&g_cnt[i1], 1); g_list[i1 * Tn + pos1] = p1;
    }
}

// ---------------- unified mma.sync GEMM (single-MMA fp16) -------------------
// MODE 0: expert gate+up FUSED  A=x(gather)  B=gw|uw interleaved   K=2048 -> Hm
// MODE 1: shared gate+up FUSED  A=x          B=sgw|suw interleaved K=2048 -> Sm
// MODE 2: expert down           A=Hm         B=dw                  K=1024 -> g_Y
// MODE 3: shared down           A=Sm         B=sdw                 K=4096 -> out (+Y)
template<int MODE>
__global__ __launch_bounds__(NTH, 2) void k_gemm(float* __restrict__ out) {
    extern __shared__ __align__(1024) char smem[];
    const uint32_t sb = smem_u32(smem);
    const int tid = threadIdx.x, wid = tid >> 5, lane = tid & 31;

    constexpr bool EXP = (MODE == 0 || MODE == 2);
    constexpr bool GUP = (MODE == 0 || MODE == 1);
    constexpr int  KT  = GUP ? 2048 : (MODE == 2 ? 1024 : 4096);
    constexpr int  NKC = KT / 32;

    const int e   = EXP ? blockIdx.z : 0;
    const int cnt = EXP ? g_cnt[e] : Tn;
    const int m0  = blockIdx.x * BM;
    if (EXP && m0 >= cnt) return;
    const int n0  = GUP ? blockIdx.y * 64 : blockIdx.y * 128;

    int* sl = (int*)(smem + SM_LIST);
    if (EXP) {
        if (tid < 128) sl[tid] = (m0 + tid < cnt) ? g_list[e * Tn + m0 + tid] : -1;
        __syncthreads();
    }

    // ---- per-thread cp.async source rows (row = tid>>1, sub = tid&1) ----
    const int arow = tid >> 1, sub = tid & 1;
    bool aval = true;
    const __half *aF, *bF;
    if (MODE == 0) {
        int p = sl[arow]; aval = (p >= 0);
        aF = g_xF + (size_t)(aval ? (p >> 1) : 0) * Hd;
    } else if (MODE == 1) {
        aF = g_xF + (size_t)(m0 + arow) * Hd;
    } else if (MODE == 2) {
        int p = sl[arow]; aval = (p >= 0);
        aF = g_Hm + (size_t)(aval ? p : 0) * Id;
    } else {
        aF = g_Sm + (size_t)(m0 + arow) * ISd;
    }
    if (GUP) {
        const int j = (arow >> 3) & 1;
        const int srow = n0 + (arow >> 4) * 8 + (arow & 7);
        if (MODE == 0) bF = (j ? g_uwF : g_gwF) + ((size_t)e * Id + srow) * Hd;
        else           bF = (j ? g_suwF : g_sgwF) + (size_t)srow * Hd;
    } else if (MODE == 2) {
        bF = g_dwF + ((size_t)e * Hd + n0 + arow) * Id;
    } else {
        bF = g_sdwF + (size_t)(n0 + arow) * ISd;
    }

    const uint32_t avB = aval ? 16u : 0u;
    // store offsets: 64B rows, swizzle on (row>>1)&3 (same scheme A and B)
    const uint32_t rsw = (uint32_t)((arow >> 1) & 3) << 4;
    const uint32_t s0 = ((uint32_t)(sub * 32))      ^ rsw;
    const uint32_t s1 = ((uint32_t)(sub * 32 + 16)) ^ rsw;
    const uint32_t aDst0 = sb + arow * 64;
    const uint32_t bDst0 = sb + SM_BOFF + arow * 64;

    // ---- mma-side ldmatrix bases ----
    const int wm = wid & 3, wn = wid >> 2;
    const uint32_t aLmRow = wm * 32 + (lane & 15);
    const uint32_t aLmB = aLmRow * 64;
    const uint32_t aswL = (uint32_t)((aLmRow >> 1) & 3) << 4;
    const uint32_t aLmK = (lane >> 4) * 16;
    const uint32_t bLmRow = wn * 64 + ((lane >> 4) & 1) * 8 + (lane & 7);
    const uint32_t bLmB = SM_BOFF + bLmRow * 64;
    const uint32_t bswL = (uint32_t)((bLmRow >> 1) & 3) << 4;
    const uint32_t bCol = ((lane >> 3) & 1) * 16;

    float acc[2][8][4];
    #pragma unroll
    for (int mt = 0; mt < 2; mt++)
        #pragma unroll
        for (int nt = 0; nt < 8; nt++)
            #pragma unroll
            for (int j = 0; j < 4; j++) acc[mt][nt][j] = 0.f;

    auto ISSUE = [&](int kc, int st) {
        const uint32_t aD = aDst0 + st * SM_STAGE;
        const uint32_t bD = bDst0 + st * SM_STAGE;
        const char* sA = (const char*)aF + kc * 64 + sub * 32;
        const char* sB = (const char*)bF + kc * 64 + sub * 32;
        cpa16(aD + s0, sA, avB);      cpa16(aD + s1, sA + 16, avB);
        cpa16(bD + s0, sB, 16u);      cpa16(bD + s1, sB + 16, 16u);
        cpcommit();
    };

    auto MMA = [&](int st) {
        const uint32_t aS = sb + st * SM_STAGE;
        #pragma unroll
        for (int h = 0; h < 2; h++) {
            uns Ah[2][4];
            #pragma unroll
            for (int mt = 0; mt < 2; mt++)
                ldsm4(Ah[mt], aS + aLmB + mt * 1024 + ((h * 32 + aLmK) ^ aswL));
            #pragma unroll
            for (int ntp = 0; ntp < 4; ntp++) {
                uns B4[4];
                ldsm4(B4, aS + bLmB + ntp * 1024 + ((h * 32 + bCol) ^ bswL));
                #pragma unroll
                for (int j = 0; j < 2; j++) {
                    const int nt = ntp * 2 + j;
                    #pragma unroll
                    for (int mt = 0; mt < 2; mt++)
                        mma16816(acc[mt][nt], Ah[mt], B4 + j * 2);
                }
            }
        }
    };

    // 4-stage pipeline, one barrier per chunk, up to 3 chunks in flight.
    ISSUE(0, 0); ISSUE(1, 1); ISSUE(2, 2);
    for (int kc = 0; kc < NKC; kc++) {
        if (kc + 1 >= NKC)      cpwait<0>();
        else if (kc + 2 >= NKC) cpwait<1>();
        else                    cpwait<2>();
        __syncthreads();
        if (kc + 3 < NKC) ISSUE(kc + 3, (kc + 3) & 3);
        MMA(kc & 3);
    }

    // ---- epilogue ----
    const int rb = wm * 32 + (lane >> 2);
    const int cq = (lane & 3) * 2;
    #pragma unroll
    for (int mt = 0; mt < 2; mt++) {
        #pragma unroll
        for (int rr = 0; rr < 2; rr++) {
            const int row = rb + mt * 16 + rr * 8;
            if (GUP) {
                float s; size_t base;
                if (MODE == 0) {
                    int p = sl[row];
                    if (p < 0) continue;
                    s = g_scores[p];
                    base = (size_t)p * Id;
                } else {
                    s = 1.f;
                    base = (size_t)(m0 + row) * ISd;
                }
                #pragma unroll
                for (int i = 0; i < 4; i++) {
                    float g0 = acc[mt][2 * i][rr * 2],     g1 = acc[mt][2 * i][rr * 2 + 1];
                    float u0 = acc[mt][2 * i + 1][rr * 2], u1 = acc[mt][2 * i + 1][rr * 2 + 1];
                    float h0, h1;
                    if (MODE == 0) { h0 = siluf(s * g0) * (s * u0); h1 = siluf(s * g1) * (s * u1); }
                    else           { h0 = siluf(g0) * u0;           h1 = siluf(g1) * u1; }
                    __half2 hp = __floats2half2_rn(h0, h1);
                    size_t idx = base + (size_t)(n0 + (wn * 4 + i) * 8 + cq);
                    if (MODE == 0) *(uns*)(g_Hm + idx) = *reinterpret_cast<uns*>(&hp);
                    else           *(uns*)(g_Sm + idx) = *reinterpret_cast<uns*>(&hp);
                }
            } else if (MODE == 2) {
                int p = sl[row];
                if (p < 0) continue;
                float* dst = g_Y + (size_t)p * Hd + n0 + wn * 64 + cq;
                #pragma unroll
                for (int nt = 0; nt < 8; nt++)
                    *(float2*)(dst + nt * 8) =
                        make_float2(acc[mt][nt][rr * 2], acc[mt][nt][rr * 2 + 1]);
            } else {
                const int t = m0 + row;
                size_t col = (size_t)(n0 + wn * 64 + cq);
                const float* y0 = g_Y + (size_t)(2 * t) * Hd + col;
                const float* y1 = g_Y + (size_t)(2 * t + 1) * Hd + col;
                float* dst = out + (size_t)t * Hd + col;
                #pragma unroll
                for (int nt = 0; nt < 8; nt++) {
                    float2 a = make_float2(acc[mt][nt][rr * 2], acc[mt][nt][rr * 2 + 1]);
                    float2 p0 = *(const float2*)(y0 + nt * 8);
                    float2 p1 = *(const float2*)(y1 + nt * 8);
                    a.x += p0.x + p1.x; a.y += p0.y + p1.y;
                    *(float2*)(dst + nt * 8) = a;
                }
            }
        }
    }
}

// ---------------- launch ----------------------------------------------------
extern "C" void kernel_launch(void* const* d_in, const int* in_sizes, int n_in,
                              void* d_out, int out_size) {
    const float* x   = (const float*)d_in[0];
    const float* rw  = (const float*)d_in[1];
    const float* gw  = (const float*)d_in[2];
    const float* uw  = (const float*)d_in[3];
    const float* dw  = (const float*)d_in[4];
    const float* sgw = (const float*)d_in[5];
    const float* suw = (const float*)d_in[6];
    const float* sdw = (const float*)d_in[7];
    float* out = (float*)d_out;
    float* logits = out + (size_t)Tn * Hd;

    cudaFuncSetAttribute(k_gemm<0>, cudaFuncAttributeMaxDynamicSharedMemorySize, SMEM_BYTES);
    cudaFuncSetAttribute(k_gemm<1>, cudaFuncAttributeMaxDynamicSharedMemorySize, SMEM_BYTES);
    cudaFuncSetAttribute(k_gemm<2>, cudaFuncAttributeMaxDynamicSharedMemorySize, SMEM_BYTES);
    cudaFuncSetAttribute(k_gemm<3>, cudaFuncAttributeMaxDynamicSharedMemorySize, SMEM_BYTES);

    __half *xF, *gwF, *uwF, *dwF, *sgwF, *suwF, *sdwF;
    cudaGetSymbolAddress((void**)&xF, g_xF);
    cudaGetSymbolAddress((void**)&gwF, g_gwF); cudaGetSymbolAddress((void**)&uwF, g_uwF);
    cudaGetSymbolAddress((void**)&dwF, g_dwF);
    cudaGetSymbolAddress((void**)&sgwF, g_sgwF); cudaGetSymbolAddress((void**)&suwF, g_suwF);
    cudaGetSymbolAddress((void**)&sdwF, g_sdwF);

    k_zero<<<1, 32>>>();
    k_router<<<Tn, 256>>>(x, rw, logits);

    const int nX = Tn * Hd / 4, nW = En * Id * Hd / 4, nS = ISd * Hd / 4;
    k_cvt<<<nX / 256, 256>>>((const float4*)x,   (uint2*)xF,   nX);
    k_cvt<<<nW / 256, 256>>>((const float4*)gw,  (uint2*)gwF,  nW);
    k_cvt<<<nW / 256, 256>>>((const float4*)uw,  (uint2*)uwF,  nW);
    k_cvt<<<nW / 256, 256>>>((const float4*)dw,  (uint2*)dwF,  nW);
    k_cvt<<<nS / 256, 256>>>((const float4*)sgw, (uint2*)sgwF, nS);
    k_cvt<<<nS / 256, 256>>>((const float4*)suw, (uint2*)suwF, nS);
    k_cvt<<<nS / 256, 256>>>((const float4*)sdw, (uint2*)sdwF, nS);

    k_gemm<0><<<dim3(Tn / BM, Id / 64, En),  NTH, SMEM_BYTES>>>(nullptr);
    k_gemm<2><<<dim3(Tn / BM, Hd / 128, En), NTH, SMEM_BYTES>>>(nullptr);
    k_gemm<1><<<dim3(Tn / BM, ISd / 64, 1),  NTH, SMEM_BYTES>>>(nullptr);
    k_gemm<3><<<dim3(Tn / BM, Hd / 128, 1),  NTH, SMEM_BYTES>>>(out);
}